// round 8
// baseline (speedup 1.0000x reference)
#include <cuda_runtime.h>
#include <cuda_bf16.h>
#include <cstdint>

#define BBATCH 16
#define CCH 512
#define M_PIX (BBATCH*64*64)     // 65536
#define NPROJ 384
#define DK 64
#define DV 256
#define NKV 1024
#define NQ  4096

// ---------------- scratch (device globals) ----------------
__device__ __align__(256) __nv_bfloat16 g_xb   [M_PIX * CCH];       // x in bf16
__device__ __align__(256) __nv_bfloat16 g_theta[M_PIX * DK];        // theta [q][64]
__device__ __align__(256) __nv_bfloat16 g_phi  [BBATCH * NKV * DK]; // pooled phi [kv][d]
__device__ __align__(256) __nv_bfloat16 g_gT   [BBATCH * DV * NKV]; // pooled g^T [d][kv]
__device__ __align__(256) __nv_bfloat16 g_ag   [M_PIX * DV];        // attn out bf16
__device__ __align__(256) __nv_bfloat16 g_wcatT[NPROJ * CCH];       // proj weights^T
__device__ __align__(256) __nv_bfloat16 g_woT  [CCH * DV];          // w_o^T
__device__ float g_bcat[NPROJ];

// ---------------- helpers ----------------
__device__ __forceinline__ uint32_t smem_u32(const void* p) {
    uint32_t a;
    asm("{ .reg .u64 t; cvta.to.shared.u64 t, %1; cvt.u32.u64 %0, t; }" : "=r"(a) : "l"(p));
    return a;
}
#define SWZ(o) ((o) ^ (((o) >> 3) & 0x70))

__device__ __forceinline__ void ldsm_x4(uint32_t* r, uint32_t a) {
    asm volatile("ldmatrix.sync.aligned.m8n8.x4.shared.b16 {%0,%1,%2,%3}, [%4];"
        : "=r"(r[0]), "=r"(r[1]), "=r"(r[2]), "=r"(r[3]) : "r"(a));
}
__device__ __forceinline__ void mma16816(float* d, const uint32_t* a, uint32_t b0, uint32_t b1) {
    asm volatile("mma.sync.aligned.m16n8k16.row.col.f32.bf16.bf16.f32 "
        "{%0,%1,%2,%3}, {%4,%5,%6,%7}, {%8,%9}, {%0,%1,%2,%3};"
        : "+f"(d[0]), "+f"(d[1]), "+f"(d[2]), "+f"(d[3])
        : "r"(a[0]), "r"(a[1]), "r"(a[2]), "r"(a[3]), "r"(b0), "r"(b1));
}
__device__ __forceinline__ void cp16(uint32_t sa, const void* ga) {
    asm volatile("cp.async.cg.shared.global [%0], [%1], 16;" :: "r"(sa), "l"(ga));
}
#define CP_COMMIT() asm volatile("cp.async.commit_group;" ::: "memory")
#define CP_WAIT(n)  asm volatile("cp.async.wait_group %0;" :: "n"(n) : "memory")

// load [ROWS x 64] bf16 tile (row stride ld) into swizzled SMEM via cp.async
template <int ROWS>
__device__ __forceinline__ void load_tile_async(const __nv_bfloat16* __restrict__ src,
                                                size_t ld, uint32_t sbase, int tid) {
#pragma unroll
    for (int t = 0; t < ROWS / 32; t++) {
        int i = tid + t * 256;
        int row = i >> 3, c = i & 7;
        cp16(sbase + SWZ(row * 128 + c * 16), src + (size_t)row * ld + c * 8);
    }
}

// ------------- 128x128-tile bf16 HMMA GEMM, fp32 accum, 3-stage cp.async ----
// MODE 0: proj — theta direct + pooled phi + pooled/transposed gT (+bias)
// MODE 2: fp32 out = X + sig*(D+bias)
template <int MODE>
__global__ void __launch_bounds__(256, 2)
gemm128(const __nv_bfloat16* __restrict__ A, int lda,
        const __nv_bfloat16* __restrict__ B, int ldb,
        int K,
        const float* __restrict__ bias,
        const float* __restrict__ Xres, const float* __restrict__ sig,
        float* __restrict__ outf) {
    extern __shared__ char sm[];
    uint32_t base = smem_u32(sm);
    const uint32_t a_su[3] = {base, base + 16384, base + 32768};
    const uint32_t b_su[3] = {base + 49152, base + 65536, base + 81920};

    int tid = threadIdx.x, wid = tid >> 5, lane = tid & 31;
    int m0 = blockIdx.y * 128, n0 = blockIdx.x * 128;
    int wm = wid & 3, wn = wid >> 2;
    int lr = lane & 15, lc = lane >> 4;

    const __nv_bfloat16* Ab = A + (size_t)m0 * lda;
    const __nv_bfloat16* Bb = B + (size_t)n0 * ldb;

    float acc[2][8][4];
#pragma unroll
    for (int i = 0; i < 2; i++)
#pragma unroll
        for (int j = 0; j < 8; j++)
#pragma unroll
            for (int e = 0; e < 4; e++) acc[i][j][e] = 0.f;

    const int nc = K >> 6;
    load_tile_async<128>(Ab, (size_t)lda, a_su[0], tid);
    load_tile_async<128>(Bb, (size_t)ldb, b_su[0], tid);
    CP_COMMIT();
    if (nc > 1) {
        load_tile_async<128>(Ab + 64, (size_t)lda, a_su[1], tid);
        load_tile_async<128>(Bb + 64, (size_t)ldb, b_su[1], tid);
        CP_COMMIT();
    }

#pragma unroll 3
    for (int c = 0; c < nc; c++) {
        if (c + 2 <= nc) { CP_WAIT(1); } else { CP_WAIT(0); }
        __syncthreads();

        int buf = c % 3;
        uint32_t abase = a_su[buf], bbase = b_su[buf];
#pragma unroll
        for (int k16 = 0; k16 < 4; k16++) {
            uint32_t af[2][4];
#pragma unroll
            for (int mt = 0; mt < 2; mt++)
                ldsm_x4(af[mt], abase + SWZ((wm * 32 + mt * 16 + lr) * 128 + k16 * 32 + lc * 16));
            uint32_t bf4[4][4];
#pragma unroll
            for (int nt2 = 0; nt2 < 4; nt2++)
                ldsm_x4(bf4[nt2], bbase + SWZ((wn * 64 + nt2 * 16 + lr) * 128 + k16 * 32 + lc * 16));
#pragma unroll
            for (int mt = 0; mt < 2; mt++)
#pragma unroll
                for (int nt = 0; nt < 8; nt++)
                    mma16816(acc[mt][nt], af[mt], bf4[nt >> 1][nt & 1], bf4[nt >> 1][2 + (nt & 1)]);
        }

        if (c + 2 < nc) {
            int nb = (c + 2) % 3;
            load_tile_async<128>(Ab + (c + 2) * 64, (size_t)lda, a_su[nb], tid);
            load_tile_async<128>(Bb + (c + 2) * 64, (size_t)ldb, b_su[nb], tid);
            CP_COMMIT();
        }
    }

    if (MODE == 2) {
        float s = sig[0];
        int r0 = m0 + wm * 32 + (lane >> 2);
        int c0 = n0 + wn * 64 + (lane & 3) * 2;
#pragma unroll
        for (int mt = 0; mt < 2; mt++) {
#pragma unroll
            for (int half = 0; half < 2; half++) {
                int row = r0 + mt * 16 + half * 8;
#pragma unroll
                for (int nt = 0; nt < 8; nt++) {
                    int col = c0 + nt * 8;
                    const float* xr = Xres + (size_t)row * CCH + col;
                    float2 xv = *(const float2*)xr;
                    float2 o;
                    o.x = xv.x + s * (acc[mt][nt][half * 2 + 0] + bias[col]);
                    o.y = xv.y + s * (acc[mt][nt][half * 2 + 1] + bias[col + 1]);
                    *(float2*)(outf + (size_t)row * CCH + col) = o;
                }
            }
        }
    }

    if (MODE == 0) {
        // proj epilogue with fused pooling
        int b = m0 >> 12;
        int kv0 = ((m0 >> 7) & 31) * 32;   // 32 pool windows per tile
        __nv_bfloat16* st = (__nv_bfloat16*)sm;
        __syncthreads();

        if (blockIdx.x == 0) {
            if (wn == 0) {
#pragma unroll
                for (int mt = 0; mt < 2; mt++)
#pragma unroll
                    for (int half = 0; half < 2; half++) {
                        int row = m0 + wm * 32 + (lane >> 2) + mt * 16 + half * 8;
#pragma unroll
                        for (int nt = 0; nt < 8; nt++) {
                            int col = nt * 8 + (lane & 3) * 2;
                            *(__nv_bfloat162*)(g_theta + (size_t)row * DK + col) =
                                __floats2bfloat162_rn(acc[mt][nt][half * 2] + bias[col],
                                                      acc[mt][nt][half * 2 + 1] + bias[col + 1]);
                        }
                    }
            } else {
#pragma unroll
                for (int mt = 0; mt < 2; mt++)
#pragma unroll
                    for (int half = 0; half < 2; half++) {
                        int lrow = wm * 32 + (lane >> 2) + mt * 16 + half * 8;
#pragma unroll
                        for (int nt = 0; nt < 8; nt++) {
                            int lcol = nt * 8 + (lane & 3) * 2;   // 0..63
                            *(__nv_bfloat162*)(st + lrow * 72 + lcol) =
                                __floats2bfloat162_rn(acc[mt][nt][half * 2] + bias[64 + lcol],
                                                      acc[mt][nt][half * 2 + 1] + bias[65 + lcol]);
                        }
                    }
            }
            __syncthreads();
            int w = tid >> 3, d8 = (tid & 7) * 8;
            __align__(16) __nv_bfloat16 o[8];
#pragma unroll
            for (int j = 0; j < 8; j++) {
                int d = d8 + j;
                o[j] = __hmax(__hmax(st[(2 * w) * 72 + d], st[(2 * w + 1) * 72 + d]),
                              __hmax(st[(64 + 2 * w) * 72 + d], st[(65 + 2 * w) * 72 + d]));
            }
            *(uint4*)(g_phi + ((size_t)(b * NKV + kv0 + w)) * DK + d8) = *(uint4*)o;
        } else {
#pragma unroll
            for (int mt = 0; mt < 2; mt++)
#pragma unroll
                for (int half = 0; half < 2; half++) {
                    int lrow = wm * 32 + (lane >> 2) + mt * 16 + half * 8;
#pragma unroll
                    for (int nt = 0; nt < 8; nt++) {
                        int lcol = wn * 64 + nt * 8 + (lane & 3) * 2;   // 0..127
                        *(__nv_bfloat162*)(st + lrow * 130 + lcol) =
                            __floats2bfloat162_rn(acc[mt][nt][half * 2] + bias[n0 + lcol],
                                                  acc[mt][nt][half * 2 + 1] + bias[n0 + lcol + 1]);
                    }
                }
            __syncthreads();
            int dl = tid & 127, kvh = tid >> 7;
            int dg = (blockIdx.x - 1) * 128 + dl;
            __align__(16) __nv_bfloat16 o[16];
#pragma unroll
            for (int i = 0; i < 16; i++) {
                int w = kvh * 16 + i;
                o[i] = __hmax(__hmax(st[(2 * w) * 130 + dl], st[(2 * w + 1) * 130 + dl]),
                              __hmax(st[(64 + 2 * w) * 130 + dl], st[(65 + 2 * w) * 130 + dl]));
            }
            __nv_bfloat16* dst = g_gT + ((size_t)(b * DV + dg)) * NKV + kv0 + kvh * 16;
            *(uint4*)dst = ((uint4*)o)[0];
            *(uint4*)(dst + 8) = ((uint4*)o)[1];
        }
    }
}

// ------------- fused attention: ag = softmax(theta phi^T) g ----------------
// CTA = 64 queries; loop 16 KV chunks of 64. theta frags hoisted; P double-buffered.
#define ATTN_SMEM (107264)
__global__ void __launch_bounds__(256, 2) attn_fused() {
    extern __shared__ char sm[];
    uint32_t base = smem_u32(sm);
    const uint32_t th_s = base;
    const uint32_t ph_s[2] = {base + 8192, base + 16384};
    const uint32_t gt_s[2] = {base + 24576, base + 57344};
    const uint32_t p_s[2] = {base + 90112, base + 98304};
    float* wsum = (float*)(sm + 106496);   // [2][64]
    float* rinv = (float*)(sm + 107008);   // [64]

    int tid = threadIdx.x, wid = tid >> 5, lane = tid & 31;
    int lr = lane & 15, lc = lane >> 4;
    int mbase = blockIdx.x * 64;
    int b = blockIdx.x >> 6;
    int wm = wid & 3, wn = wid >> 2;       // S phase
    int pm = wid & 1, pn = wid >> 1;       // PV phase

    const __nv_bfloat16* thp = g_theta + (size_t)mbase * DK;
    const __nv_bfloat16* php = g_phi + (size_t)b * NKV * DK;
    const __nv_bfloat16* gtp = g_gT + (size_t)b * DV * NKV;

    float O[2][8][4];
#pragma unroll
    for (int i = 0; i < 2; i++)
#pragma unroll
        for (int j = 0; j < 8; j++)
#pragma unroll
            for (int e = 0; e < 4; e++) O[i][j][e] = 0.f;
    float sum0 = 0.f, sum1 = 0.f;

    // prologue: theta + chunk 0, then hoist theta fragments
    load_tile_async<64>(thp, DK, th_s, tid);
    load_tile_async<64>(php, DK, ph_s[0], tid);
    load_tile_async<256>(gtp, NKV, gt_s[0], tid);
    CP_COMMIT();
    CP_WAIT(0);
    __syncthreads();

    uint32_t af_th[4][4];
#pragma unroll
    for (int k16 = 0; k16 < 4; k16++)
        ldsm_x4(af_th[k16], th_s + SWZ((wm * 16 + lr) * 128 + k16 * 32 + lc * 16));

#pragma unroll 2
    for (int c = 0; c < 16; c++) {
        if (c + 1 < 16) {   // prefetch chunk c+1 (overlaps S+PV of c)
            int nb = (c + 1) & 1;
            load_tile_async<64>(php + (size_t)(c + 1) * 64 * DK, DK, ph_s[nb], tid);
            load_tile_async<256>(gtp + (c + 1) * 64, NKV, gt_s[nb], tid);
            CP_COMMIT();
        }

        // ---- S phase ----
        float sacc[4][4];
#pragma unroll
        for (int j = 0; j < 4; j++)
#pragma unroll
            for (int e = 0; e < 4; e++) sacc[j][e] = 0.f;
        uint32_t pb = ph_s[c & 1];
#pragma unroll
        for (int k16 = 0; k16 < 4; k16++) {
            uint32_t bf2[2][4];
#pragma unroll
            for (int nt2 = 0; nt2 < 2; nt2++)
                ldsm_x4(bf2[nt2], pb + SWZ((wn * 32 + nt2 * 16 + lr) * 128 + k16 * 32 + lc * 16));
#pragma unroll
            for (int nt = 0; nt < 4; nt++)
                mma16816(sacc[nt], af_th[k16], bf2[nt >> 1][nt & 1], bf2[nt >> 1][2 + (nt & 1)]);
        }

        int srow = wm * 16 + (lane >> 2);
        uint32_t pw = p_s[c & 1];
#pragma unroll
        for (int nt = 0; nt < 4; nt++) {
            int scol = wn * 32 + nt * 8 + (lane & 3) * 2;
            float e0 = __expf(sacc[nt][0]);
            float e1 = __expf(sacc[nt][1]);
            float e2 = __expf(sacc[nt][2]);
            float e3 = __expf(sacc[nt][3]);
            sum0 += e0 + e1;
            sum1 += e2 + e3;
            *(__nv_bfloat162*)(sm + (pw - base) + SWZ(srow * 128 + scol * 2)) =
                __floats2bfloat162_rn(e0, e1);
            *(__nv_bfloat162*)(sm + (pw - base) + SWZ((srow + 8) * 128 + scol * 2)) =
                __floats2bfloat162_rn(e2, e3);
        }
        __syncthreads();   // P(c) visible to all warps

        // ---- PV phase ----
        uint32_t gb = gt_s[c & 1];
#pragma unroll
        for (int k16 = 0; k16 < 4; k16++) {
            uint32_t paf[2][4];
#pragma unroll
            for (int mt = 0; mt < 2; mt++)
                ldsm_x4(paf[mt], pw + SWZ((pm * 32 + mt * 16 + lr) * 128 + k16 * 32 + lc * 16));
            uint32_t gbf[4][4];
#pragma unroll
            for (int nt2 = 0; nt2 < 4; nt2++)
                ldsm_x4(gbf[nt2], gb + SWZ((pn * 64 + nt2 * 16 + lr) * 128 + k16 * 32 + lc * 16));
#pragma unroll
            for (int mt = 0; mt < 2; mt++)
#pragma unroll
                for (int nt = 0; nt < 8; nt++)
                    mma16816(O[mt][nt], paf[mt], gbf[nt >> 1][nt & 1], gbf[nt >> 1][2 + (nt & 1)]);
        }

        CP_WAIT(0);        // chunk c+1 loads landed
        __syncthreads();   // all warps past PV(c); loads visible
    }

    // deterministic row-sum reduction
    sum0 += __shfl_xor_sync(0xffffffffu, sum0, 1);
    sum0 += __shfl_xor_sync(0xffffffffu, sum0, 2);
    sum1 += __shfl_xor_sync(0xffffffffu, sum1, 1);
    sum1 += __shfl_xor_sync(0xffffffffu, sum1, 2);
    if ((lane & 3) == 0) {
        wsum[wn * 64 + wm * 16 + (lane >> 2)] = sum0;
        wsum[wn * 64 + wm * 16 + 8 + (lane >> 2)] = sum1;
    }
    __syncthreads();
    if (tid < 64) rinv[tid] = 1.f / (wsum[tid] + wsum[64 + tid]);
    __syncthreads();

#pragma unroll
    for (int mt = 0; mt < 2; mt++) {
#pragma unroll
        for (int half = 0; half < 2; half++) {
            int row = pm * 32 + mt * 16 + half * 8 + (lane >> 2);
            float rs = rinv[row];
            __nv_bfloat16* dst = g_ag + (size_t)(mbase + row) * DV;
#pragma unroll
            for (int nt = 0; nt < 8; nt++) {
                int col = pn * 64 + nt * 8 + (lane & 3) * 2;
                *(__nv_bfloat162*)(dst + col) = __floats2bfloat162_rn(
                    O[mt][nt][half * 2 + 0] * rs, O[mt][nt][half * 2 + 1] * rs);
            }
        }
    }
}

// ---------------- small kernels ----------------
__global__ void pack_kernel(const float* __restrict__ wt, const float* __restrict__ wp,
                            const float* __restrict__ wg, const float* __restrict__ bt,
                            const float* __restrict__ bp, const float* __restrict__ bg,
                            const float* __restrict__ wo) {
    int idx = blockIdx.x * blockDim.x + threadIdx.x;
    if (idx < NPROJ * CCH) {
        int n = idx / CCH, k = idx - n * CCH;
        float v;
        if (n < 64)       v = wt[k * 64 + n];
        else if (n < 128) v = wp[k * 64 + (n - 64)];
        else              v = wg[k * 256 + (n - 128)];
        g_wcatT[idx] = __float2bfloat16(v);
    }
    if (idx < CCH * DV) {
        int n = idx / DV, k = idx - n * DV;
        g_woT[idx] = __float2bfloat16(wo[k * CCH + n]);
    }
    if (idx < NPROJ) {
        float v;
        if (idx < 64)       v = bt[idx];
        else if (idx < 128) v = bp[idx - 64];
        else                v = bg[idx - 128];
        g_bcat[idx] = v;
    }
}

__global__ void xconv_kernel(const float* __restrict__ x) {
    int i = blockIdx.x * blockDim.x + threadIdx.x;
    if (i >= M_PIX * CCH / 8) return;
    float4 a = *(const float4*)(x + (size_t)i * 8);
    float4 b = *(const float4*)(x + (size_t)i * 8 + 4);
    __nv_bfloat162 h[4];
    h[0] = __floats2bfloat162_rn(a.x, a.y);
    h[1] = __floats2bfloat162_rn(a.z, a.w);
    h[2] = __floats2bfloat162_rn(b.x, b.y);
    h[3] = __floats2bfloat162_rn(b.z, b.w);
    *(uint4*)(g_xb + (size_t)i * 8) = *(uint4*)h;
}

// ---------------- launcher ----------------
extern "C" void kernel_launch(void* const* d_in, const int* in_sizes, int n_in,
                              void* d_out, int out_size) {
    const float* x       = (const float*)d_in[0];
    const float* w_theta = (const float*)d_in[1];
    const float* b_theta = (const float*)d_in[2];
    const float* w_phi   = (const float*)d_in[3];
    const float* b_phi   = (const float*)d_in[4];
    const float* w_g     = (const float*)d_in[5];
    const float* b_g     = (const float*)d_in[6];
    const float* w_o     = (const float*)d_in[7];
    const float* b_o     = (const float*)d_in[8];
    const float* sigma   = (const float*)d_in[9];
    float* out = (float*)d_out;

    const int SMEM128 = 98304;
    cudaFuncSetAttribute((const void*)gemm128<0>, cudaFuncAttributeMaxDynamicSharedMemorySize, SMEM128);
    cudaFuncSetAttribute((const void*)gemm128<2>, cudaFuncAttributeMaxDynamicSharedMemorySize, SMEM128);
    cudaFuncSetAttribute((const void*)attn_fused, cudaFuncAttributeMaxDynamicSharedMemorySize, ATTN_SMEM);

    __nv_bfloat16 *xb, *ag, *wcatT, *woT;
    float* bcat;
    cudaGetSymbolAddress((void**)&xb, g_xb);
    cudaGetSymbolAddress((void**)&ag, g_ag);
    cudaGetSymbolAddress((void**)&wcatT, g_wcatT);
    cudaGetSymbolAddress((void**)&woT, g_woT);
    cudaGetSymbolAddress((void**)&bcat, g_bcat);

    pack_kernel<<<(NPROJ * CCH + 255) / 256, 256>>>(w_theta, w_phi, w_g,
                                                    b_theta, b_phi, b_g, w_o);
    xconv_kernel<<<M_PIX * CCH / 8 / 256, 256>>>(x);

    // proj (+fused pooling): theta/phi/gT produced directly
    gemm128<0><<<dim3(NPROJ / 128, M_PIX / 128), 256, SMEM128>>>(
        xb, CCH, wcatT, CCH, CCH, bcat, nullptr, nullptr, nullptr);

    // fused attention: ag = softmax(theta phi^T) g
    attn_fused<<<M_PIX / 64, 256, ATTN_SMEM>>>();

    // out: [65536, 512] = x + sigma * (ag[65536,256] @ woT[512,256]^T + b_o)
    gemm128<2><<<dim3(CCH / 128, M_PIX / 128), 256, SMEM128>>>(
        ag, DV, woT, DV, DV, b_o, x, sigma, out);
}

// round 9
// speedup vs baseline: 1.0855x; 1.0855x over previous
#include <cuda_runtime.h>
#include <cuda_bf16.h>
#include <cstdint>

#define BBATCH 16
#define CCH 512
#define M_PIX (BBATCH*64*64)     // 65536
#define NPROJ 384
#define DK 64
#define DV 256
#define NKV 1024
#define NQ  4096

// ---------------- scratch (device globals) ----------------
__device__ __align__(256) __nv_bfloat16 g_xb   [M_PIX * CCH];       // x in bf16
__device__ __align__(256) __nv_bfloat16 g_theta[M_PIX * DK];        // theta [q][64]
__device__ __align__(256) __nv_bfloat16 g_phi  [BBATCH * NKV * DK]; // pooled phi [kv][d]
__device__ __align__(256) __nv_bfloat16 g_gT   [BBATCH * DV * NKV]; // pooled g^T [d][kv]
__device__ __align__(256) __nv_bfloat16 g_ag   [M_PIX * DV];        // attn out bf16
__device__ __align__(256) __nv_bfloat16 g_wcatT[NPROJ * CCH];       // proj weights^T
__device__ __align__(256) __nv_bfloat16 g_woT  [CCH * DV];          // w_o^T
__device__ float g_bcat[NPROJ];

// ---------------- helpers ----------------
__device__ __forceinline__ uint32_t smem_u32(const void* p) {
    uint32_t a;
    asm("{ .reg .u64 t; cvta.to.shared.u64 t, %1; cvt.u32.u64 %0, t; }" : "=r"(a) : "l"(p));
    return a;
}
#define SWZ(o) ((o) ^ (((o) >> 3) & 0x70))

__device__ __forceinline__ void ldsm_x4(uint32_t* r, uint32_t a) {
    asm volatile("ldmatrix.sync.aligned.m8n8.x4.shared.b16 {%0,%1,%2,%3}, [%4];"
        : "=r"(r[0]), "=r"(r[1]), "=r"(r[2]), "=r"(r[3]) : "r"(a));
}
__device__ __forceinline__ void mma16816(float* d, const uint32_t* a, uint32_t b0, uint32_t b1) {
    asm volatile("mma.sync.aligned.m16n8k16.row.col.f32.bf16.bf16.f32 "
        "{%0,%1,%2,%3}, {%4,%5,%6,%7}, {%8,%9}, {%0,%1,%2,%3};"
        : "+f"(d[0]), "+f"(d[1]), "+f"(d[2]), "+f"(d[3])
        : "r"(a[0]), "r"(a[1]), "r"(a[2]), "r"(a[3]), "r"(b0), "r"(b1));
}
__device__ __forceinline__ void cp16(uint32_t sa, const void* ga) {
    asm volatile("cp.async.cg.shared.global [%0], [%1], 16;" :: "r"(sa), "l"(ga));
}
#define CP_COMMIT() asm volatile("cp.async.commit_group;" ::: "memory")
#define CP_WAIT(n)  asm volatile("cp.async.wait_group %0;" :: "n"(n) : "memory")

__device__ __forceinline__ uint32_t packbf2(float a, float b) {
    __nv_bfloat162 h = __floats2bfloat162_rn(a, b);
    return *(uint32_t*)&h;
}

// load [ROWS x 64] bf16 tile (row stride ld) into swizzled SMEM via cp.async
template <int ROWS>
__device__ __forceinline__ void load_tile_async(const __nv_bfloat16* __restrict__ src,
                                                size_t ld, uint32_t sbase, int tid) {
#pragma unroll
    for (int t = 0; t < ROWS / 32; t++) {
        int i = tid + t * 256;
        int row = i >> 3, c = i & 7;
        cp16(sbase + SWZ(row * 128 + c * 16), src + (size_t)row * ld + c * 8);
    }
}

// ------------- 128x128-tile bf16 HMMA GEMM, fp32 accum, 3-stage cp.async ----
// MODE 0: proj — theta direct + pooled phi + pooled/transposed gT (+bias)
// MODE 2: fp32 out = X + sig*(D+bias)
template <int MODE>
__global__ void __launch_bounds__(256, 2)
gemm128(const __nv_bfloat16* __restrict__ A, int lda,
        const __nv_bfloat16* __restrict__ B, int ldb,
        int K,
        const float* __restrict__ bias,
        const float* __restrict__ Xres, const float* __restrict__ sig,
        float* __restrict__ outf) {
    extern __shared__ char sm[];
    uint32_t base = smem_u32(sm);
    const uint32_t a_su[3] = {base, base + 16384, base + 32768};
    const uint32_t b_su[3] = {base + 49152, base + 65536, base + 81920};

    int tid = threadIdx.x, wid = tid >> 5, lane = tid & 31;
    int m0 = blockIdx.y * 128, n0 = blockIdx.x * 128;
    int wm = wid & 3, wn = wid >> 2;
    int lr = lane & 15, lc = lane >> 4;

    const __nv_bfloat16* Ab = A + (size_t)m0 * lda;
    const __nv_bfloat16* Bb = B + (size_t)n0 * ldb;

    float acc[2][8][4];
#pragma unroll
    for (int i = 0; i < 2; i++)
#pragma unroll
        for (int j = 0; j < 8; j++)
#pragma unroll
            for (int e = 0; e < 4; e++) acc[i][j][e] = 0.f;

    const int nc = K >> 6;
    load_tile_async<128>(Ab, (size_t)lda, a_su[0], tid);
    load_tile_async<128>(Bb, (size_t)ldb, b_su[0], tid);
    CP_COMMIT();
    if (nc > 1) {
        load_tile_async<128>(Ab + 64, (size_t)lda, a_su[1], tid);
        load_tile_async<128>(Bb + 64, (size_t)ldb, b_su[1], tid);
        CP_COMMIT();
    }

#pragma unroll 3
    for (int c = 0; c < nc; c++) {
        if (c + 2 <= nc) { CP_WAIT(1); } else { CP_WAIT(0); }
        __syncthreads();

        int buf = c % 3;
        uint32_t abase = a_su[buf], bbase = b_su[buf];
#pragma unroll
        for (int k16 = 0; k16 < 4; k16++) {
            uint32_t af[2][4];
#pragma unroll
            for (int mt = 0; mt < 2; mt++)
                ldsm_x4(af[mt], abase + SWZ((wm * 32 + mt * 16 + lr) * 128 + k16 * 32 + lc * 16));
            uint32_t bf4[4][4];
#pragma unroll
            for (int nt2 = 0; nt2 < 4; nt2++)
                ldsm_x4(bf4[nt2], bbase + SWZ((wn * 64 + nt2 * 16 + lr) * 128 + k16 * 32 + lc * 16));
#pragma unroll
            for (int mt = 0; mt < 2; mt++)
#pragma unroll
                for (int nt = 0; nt < 8; nt++)
                    mma16816(acc[mt][nt], af[mt], bf4[nt >> 1][nt & 1], bf4[nt >> 1][2 + (nt & 1)]);
        }

        if (c + 2 < nc) {
            int nb = (c + 2) % 3;
            load_tile_async<128>(Ab + (c + 2) * 64, (size_t)lda, a_su[nb], tid);
            load_tile_async<128>(Bb + (c + 2) * 64, (size_t)ldb, b_su[nb], tid);
            CP_COMMIT();
        }
    }

    if (MODE == 2) {
        float s = sig[0];
        int r0 = m0 + wm * 32 + (lane >> 2);
        int c0 = n0 + wn * 64 + (lane & 3) * 2;
#pragma unroll
        for (int mt = 0; mt < 2; mt++) {
#pragma unroll
            for (int half = 0; half < 2; half++) {
                int row = r0 + mt * 16 + half * 8;
#pragma unroll
                for (int nt = 0; nt < 8; nt++) {
                    int col = c0 + nt * 8;
                    const float* xr = Xres + (size_t)row * CCH + col;
                    float2 xv = *(const float2*)xr;
                    float2 o;
                    o.x = xv.x + s * (acc[mt][nt][half * 2 + 0] + bias[col]);
                    o.y = xv.y + s * (acc[mt][nt][half * 2 + 1] + bias[col + 1]);
                    *(float2*)(outf + (size_t)row * CCH + col) = o;
                }
            }
        }
    }

    if (MODE == 0) {
        // proj epilogue with fused pooling
        int b = m0 >> 12;
        int kv0 = ((m0 >> 7) & 31) * 32;   // 32 pool windows per tile
        __nv_bfloat16* st = (__nv_bfloat16*)sm;
        __syncthreads();

        if (blockIdx.x == 0) {
            if (wn == 0) {
#pragma unroll
                for (int mt = 0; mt < 2; mt++)
#pragma unroll
                    for (int half = 0; half < 2; half++) {
                        int row = m0 + wm * 32 + (lane >> 2) + mt * 16 + half * 8;
#pragma unroll
                        for (int nt = 0; nt < 8; nt++) {
                            int col = nt * 8 + (lane & 3) * 2;
                            *(__nv_bfloat162*)(g_theta + (size_t)row * DK + col) =
                                __floats2bfloat162_rn(acc[mt][nt][half * 2] + bias[col],
                                                      acc[mt][nt][half * 2 + 1] + bias[col + 1]);
                        }
                    }
            } else {
#pragma unroll
                for (int mt = 0; mt < 2; mt++)
#pragma unroll
                    for (int half = 0; half < 2; half++) {
                        int lrow = wm * 32 + (lane >> 2) + mt * 16 + half * 8;
#pragma unroll
                        for (int nt = 0; nt < 8; nt++) {
                            int lcol = nt * 8 + (lane & 3) * 2;   // 0..63
                            *(__nv_bfloat162*)(st + lrow * 72 + lcol) =
                                __floats2bfloat162_rn(acc[mt][nt][half * 2] + bias[64 + lcol],
                                                      acc[mt][nt][half * 2 + 1] + bias[65 + lcol]);
                        }
                    }
            }
            __syncthreads();
            int w = tid >> 3, d8 = (tid & 7) * 8;
            __align__(16) __nv_bfloat16 o[8];
#pragma unroll
            for (int j = 0; j < 8; j++) {
                int d = d8 + j;
                o[j] = __hmax(__hmax(st[(2 * w) * 72 + d], st[(2 * w + 1) * 72 + d]),
                              __hmax(st[(64 + 2 * w) * 72 + d], st[(65 + 2 * w) * 72 + d]));
            }
            *(uint4*)(g_phi + ((size_t)(b * NKV + kv0 + w)) * DK + d8) = *(uint4*)o;
        } else {
#pragma unroll
            for (int mt = 0; mt < 2; mt++)
#pragma unroll
                for (int half = 0; half < 2; half++) {
                    int lrow = wm * 32 + (lane >> 2) + mt * 16 + half * 8;
#pragma unroll
                    for (int nt = 0; nt < 8; nt++) {
                        int lcol = wn * 64 + nt * 8 + (lane & 3) * 2;   // 0..127
                        *(__nv_bfloat162*)(st + lrow * 130 + lcol) =
                            __floats2bfloat162_rn(acc[mt][nt][half * 2] + bias[n0 + lcol],
                                                  acc[mt][nt][half * 2 + 1] + bias[n0 + lcol + 1]);
                    }
                }
            __syncthreads();
            int dl = tid & 127, kvh = tid >> 7;
            int dg = (blockIdx.x - 1) * 128 + dl;
            __align__(16) __nv_bfloat16 o[16];
#pragma unroll
            for (int i = 0; i < 16; i++) {
                int w = kvh * 16 + i;
                o[i] = __hmax(__hmax(st[(2 * w) * 130 + dl], st[(2 * w + 1) * 130 + dl]),
                              __hmax(st[(64 + 2 * w) * 130 + dl], st[(65 + 2 * w) * 130 + dl]));
            }
            __nv_bfloat16* dst = g_gT + ((size_t)(b * DV + dg)) * NKV + kv0 + kvh * 16;
            *(uint4*)dst = ((uint4*)o)[0];
            *(uint4*)(dst + 8) = ((uint4*)o)[1];
        }
    }
}

// ------------- fused attention (FA2-style register P reuse) ---------------
// CTA = 64 queries; 16 KV chunks of 64. Warps: wq = wid&3 (16 q rows),
// wd = wid>>2 (128 dv cols). Each warp computes FULL-kv S for its rows
// (duplicated across the 2 dv warps), exps in regs, packs P fragments
// directly as MMA A-operands (layout identity), accumulates its O slice.
// One __syncthreads per chunk; no P SMEM.
#define ATTN_SMEM (90368)
__global__ void __launch_bounds__(256, 2) attn_fused() {
    extern __shared__ char sm[];
    uint32_t base = smem_u32(sm);
    const uint32_t th_s = base;
    const uint32_t ph_s[2] = {base + 8192, base + 16384};
    const uint32_t gt_s[2] = {base + 24576, base + 57344};
    float* rinv = (float*)(sm + 90112);   // [64]

    int tid = threadIdx.x, wid = tid >> 5, lane = tid & 31;
    int lr = lane & 15, lc = lane >> 4;
    int mbase = blockIdx.x * 64;
    int b = blockIdx.x >> 6;
    int wq = wid & 3, wd = wid >> 2;

    const __nv_bfloat16* thp = g_theta + (size_t)mbase * DK;
    const __nv_bfloat16* php = g_phi + (size_t)b * NKV * DK;
    const __nv_bfloat16* gtp = g_gT + (size_t)b * DV * NKV;

    float O[16][4];
#pragma unroll
    for (int i = 0; i < 16; i++)
#pragma unroll
        for (int e = 0; e < 4; e++) O[i][e] = 0.f;
    float sum0 = 0.f, sum1 = 0.f;

    // prologue: theta + chunk 0
    load_tile_async<64>(thp, DK, th_s, tid);
    load_tile_async<64>(php, DK, ph_s[0], tid);
    load_tile_async<256>(gtp, NKV, gt_s[0], tid);
    CP_COMMIT();

    for (int c = 0; c < 16; c++) {
        CP_WAIT(0);
        __syncthreads();   // chunk-c tiles visible; all warps done with c-1

        if (c + 1 < 16) {  // prefetch c+1 (other buffers), overlaps compute of c
            int nb = (c + 1) & 1;
            load_tile_async<64>(php + (size_t)(c + 1) * 64 * DK, DK, ph_s[nb], tid);
            load_tile_async<256>(gtp + (c + 1) * 64, NKV, gt_s[nb], tid);
            CP_COMMIT();
        }

        // ---- S phase: S[16q x 64kv] in two kv-32 halves (register economy) ----
        uint32_t pf[8][2];
        uint32_t pb = ph_s[c & 1];
#pragma unroll
        for (int nh = 0; nh < 2; nh++) {
            float sacc[4][4];
#pragma unroll
            for (int j = 0; j < 4; j++)
#pragma unroll
                for (int e = 0; e < 4; e++) sacc[j][e] = 0.f;
#pragma unroll
            for (int k16 = 0; k16 < 4; k16++) {
                uint32_t af[4];
                ldsm_x4(af, th_s + SWZ((wq * 16 + lr) * 128 + k16 * 32 + lc * 16));
#pragma unroll
                for (int nt2 = 0; nt2 < 2; nt2++) {
                    uint32_t bf[4];
                    ldsm_x4(bf, pb + SWZ((nh * 32 + nt2 * 16 + lr) * 128 + k16 * 32 + lc * 16));
                    mma16816(sacc[nt2 * 2 + 0], af, bf[0], bf[2]);
                    mma16816(sacc[nt2 * 2 + 1], af, bf[1], bf[3]);
                }
            }
#pragma unroll
            for (int j = 0; j < 4; j++) {
                float e0 = __expf(sacc[j][0]);
                float e1 = __expf(sacc[j][1]);
                float e2 = __expf(sacc[j][2]);
                float e3 = __expf(sacc[j][3]);
                sum0 += e0 + e1;
                sum1 += e2 + e3;
                pf[nh * 4 + j][0] = packbf2(e0, e1);
                pf[nh * 4 + j][1] = packbf2(e2, e3);
            }
        }

        // ---- PV phase: O[16q x 128dv] += P @ gT^T (P frags direct from regs) ----
        uint32_t gb = gt_s[c & 1];
#pragma unroll
        for (int kt = 0; kt < 4; kt++) {
            uint32_t a[4] = {pf[2 * kt][0], pf[2 * kt][1], pf[2 * kt + 1][0], pf[2 * kt + 1][1]};
#pragma unroll
            for (int j = 0; j < 8; j++) {
                uint32_t gb4[4];
                ldsm_x4(gb4, gb + SWZ((wd * 128 + j * 16 + lr) * 128 + kt * 32 + lc * 16));
                mma16816(O[2 * j + 0], a, gb4[0], gb4[2]);
                mma16816(O[2 * j + 1], a, gb4[1], gb4[3]);
            }
        }
    }

    // ---- warp-local deterministic row sums ----
    sum0 += __shfl_xor_sync(0xffffffffu, sum0, 1);
    sum0 += __shfl_xor_sync(0xffffffffu, sum0, 2);
    sum1 += __shfl_xor_sync(0xffffffffu, sum1, 1);
    sum1 += __shfl_xor_sync(0xffffffffu, sum1, 2);
    if (wd == 0 && (lane & 3) == 0) {
        rinv[wq * 16 + (lane >> 2)] = 1.f / sum0;
        rinv[wq * 16 + 8 + (lane >> 2)] = 1.f / sum1;
    }
    __syncthreads();

    // ---- epilogue ----
    int gid = lane >> 2;
    float rs0 = rinv[wq * 16 + gid];
    float rs1 = rinv[wq * 16 + 8 + gid];
    __nv_bfloat16* dst0 = g_ag + (size_t)(mbase + wq * 16 + gid) * DV;
    __nv_bfloat16* dst1 = g_ag + (size_t)(mbase + wq * 16 + 8 + gid) * DV;
#pragma unroll
    for (int nt = 0; nt < 16; nt++) {
        int col = wd * 128 + nt * 8 + (lane & 3) * 2;
        *(__nv_bfloat162*)(dst0 + col) = __floats2bfloat162_rn(O[nt][0] * rs0, O[nt][1] * rs0);
        *(__nv_bfloat162*)(dst1 + col) = __floats2bfloat162_rn(O[nt][2] * rs1, O[nt][3] * rs1);
    }
}

// ---------------- small kernels ----------------
__global__ void pack_kernel(const float* __restrict__ wt, const float* __restrict__ wp,
                            const float* __restrict__ wg, const float* __restrict__ bt,
                            const float* __restrict__ bp, const float* __restrict__ bg,
                            const float* __restrict__ wo) {
    int idx = blockIdx.x * blockDim.x + threadIdx.x;
    if (idx < NPROJ * CCH) {
        int n = idx / CCH, k = idx - n * CCH;
        float v;
        if (n < 64)       v = wt[k * 64 + n];
        else if (n < 128) v = wp[k * 64 + (n - 64)];
        else              v = wg[k * 256 + (n - 128)];
        g_wcatT[idx] = __float2bfloat16(v);
    }
    if (idx < CCH * DV) {
        int n = idx / DV, k = idx - n * DV;
        g_woT[idx] = __float2bfloat16(wo[k * CCH + n]);
    }
    if (idx < NPROJ) {
        float v;
        if (idx < 64)       v = bt[idx];
        else if (idx < 128) v = bp[idx - 64];
        else                v = bg[idx - 128];
        g_bcat[idx] = v;
    }
}

__global__ void xconv_kernel(const float* __restrict__ x) {
    int i = blockIdx.x * blockDim.x + threadIdx.x;
    if (i >= M_PIX * CCH / 8) return;
    float4 a = *(const float4*)(x + (size_t)i * 8);
    float4 b = *(const float4*)(x + (size_t)i * 8 + 4);
    __nv_bfloat162 h[4];
    h[0] = __floats2bfloat162_rn(a.x, a.y);
    h[1] = __floats2bfloat162_rn(a.z, a.w);
    h[2] = __floats2bfloat162_rn(b.x, b.y);
    h[3] = __floats2bfloat162_rn(b.z, b.w);
    *(uint4*)(g_xb + (size_t)i * 8) = *(uint4*)h;
}

// ---------------- launcher ----------------
extern "C" void kernel_launch(void* const* d_in, const int* in_sizes, int n_in,
                              void* d_out, int out_size) {
    const float* x       = (const float*)d_in[0];
    const float* w_theta = (const float*)d_in[1];
    const float* b_theta = (const float*)d_in[2];
    const float* w_phi   = (const float*)d_in[3];
    const float* b_phi   = (const float*)d_in[4];
    const float* w_g     = (const float*)d_in[5];
    const float* b_g     = (const float*)d_in[6];
    const float* w_o     = (const float*)d_in[7];
    const float* b_o     = (const float*)d_in[8];
    const float* sigma   = (const float*)d_in[9];
    float* out = (float*)d_out;

    const int SMEM128 = 98304;
    cudaFuncSetAttribute((const void*)gemm128<0>, cudaFuncAttributeMaxDynamicSharedMemorySize, SMEM128);
    cudaFuncSetAttribute((const void*)gemm128<2>, cudaFuncAttributeMaxDynamicSharedMemorySize, SMEM128);
    cudaFuncSetAttribute((const void*)attn_fused, cudaFuncAttributeMaxDynamicSharedMemorySize, ATTN_SMEM);

    __nv_bfloat16 *xb, *ag, *wcatT, *woT;
    float* bcat;
    cudaGetSymbolAddress((void**)&xb, g_xb);
    cudaGetSymbolAddress((void**)&ag, g_ag);
    cudaGetSymbolAddress((void**)&wcatT, g_wcatT);
    cudaGetSymbolAddress((void**)&woT, g_woT);
    cudaGetSymbolAddress((void**)&bcat, g_bcat);

    pack_kernel<<<(NPROJ * CCH + 255) / 256, 256>>>(w_theta, w_phi, w_g,
                                                    b_theta, b_phi, b_g, w_o);
    xconv_kernel<<<M_PIX * CCH / 8 / 256, 256>>>(x);

    // proj (+fused pooling): theta/phi/gT produced directly
    gemm128<0><<<dim3(NPROJ / 128, M_PIX / 128), 256, SMEM128>>>(
        xb, CCH, wcatT, CCH, CCH, bcat, nullptr, nullptr, nullptr);

    // fused attention: ag = softmax(theta phi^T) g
    attn_fused<<<M_PIX / 64, 256, ATTN_SMEM>>>();

    // out: [65536, 512] = x + sigma * (ag[65536,256] @ woT[512,256]^T + b_o)
    gemm128<2><<<dim3(CCH / 128, M_PIX / 128), 256, SMEM128>>>(
        ag, DV, woT, DV, DV, b_o, x, sigma, out);
}

// round 10
// speedup vs baseline: 1.1412x; 1.0513x over previous
#include <cuda_runtime.h>
#include <cuda_bf16.h>
#include <cstdint>

#define BBATCH 16
#define CCH 512
#define M_PIX (BBATCH*64*64)     // 65536
#define NPROJ 384
#define DK 64
#define DV 256
#define NKV 1024
#define NQ  4096

// ---------------- scratch (device globals) ----------------
__device__ __align__(256) __nv_bfloat16 g_xb   [M_PIX * CCH];       // x in bf16
__device__ __align__(256) __nv_bfloat16 g_theta[M_PIX * DK];        // theta [q][64]
__device__ __align__(256) __nv_bfloat16 g_phi  [BBATCH * NKV * DK]; // pooled phi [kv][d]
__device__ __align__(256) __nv_bfloat16 g_gT   [BBATCH * DV * NKV]; // pooled g^T [d][kv]
__device__ __align__(256) __nv_bfloat16 g_ag   [M_PIX * DV];        // attn out bf16
__device__ __align__(256) __nv_bfloat16 g_wcatT[NPROJ * CCH];       // proj weights^T
__device__ __align__(256) __nv_bfloat16 g_woT  [CCH * DV];          // w_o^T
__device__ float g_bcat[NPROJ];

// ---------------- helpers ----------------
__device__ __forceinline__ uint32_t smem_u32(const void* p) {
    uint32_t a;
    asm("{ .reg .u64 t; cvta.to.shared.u64 t, %1; cvt.u32.u64 %0, t; }" : "=r"(a) : "l"(p));
    return a;
}
#define SWZ(o) ((o) ^ (((o) >> 3) & 0x70))

__device__ __forceinline__ void ldsm_x4(uint32_t* r, uint32_t a) {
    asm volatile("ldmatrix.sync.aligned.m8n8.x4.shared.b16 {%0,%1,%2,%3}, [%4];"
        : "=r"(r[0]), "=r"(r[1]), "=r"(r[2]), "=r"(r[3]) : "r"(a));
}
__device__ __forceinline__ void mma16816(float* d, const uint32_t* a, uint32_t b0, uint32_t b1) {
    asm volatile("mma.sync.aligned.m16n8k16.row.col.f32.bf16.bf16.f32 "
        "{%0,%1,%2,%3}, {%4,%5,%6,%7}, {%8,%9}, {%0,%1,%2,%3};"
        : "+f"(d[0]), "+f"(d[1]), "+f"(d[2]), "+f"(d[3])
        : "r"(a[0]), "r"(a[1]), "r"(a[2]), "r"(a[3]), "r"(b0), "r"(b1));
}
__device__ __forceinline__ void cp16(uint32_t sa, const void* ga) {
    asm volatile("cp.async.cg.shared.global [%0], [%1], 16;" :: "r"(sa), "l"(ga));
}
#define CP_COMMIT() asm volatile("cp.async.commit_group;" ::: "memory")
#define CP_WAIT(n)  asm volatile("cp.async.wait_group %0;" :: "n"(n) : "memory")

// load [ROWS x 64] bf16 tile (row stride ld) into swizzled SMEM via cp.async
template <int ROWS>
__device__ __forceinline__ void load_tile_async(const __nv_bfloat16* __restrict__ src,
                                                size_t ld, uint32_t sbase, int tid) {
#pragma unroll
    for (int t = 0; t < ROWS / 32; t++) {
        int i = tid + t * 256;
        int row = i >> 3, c = i & 7;
        cp16(sbase + SWZ(row * 128 + c * 16), src + (size_t)row * ld + c * 8);
    }
}

// ------------- 128x128-tile bf16 HMMA GEMM, fp32 accum, 3-stage cp.async ----
// MODE 0: proj — theta direct + pooled phi + pooled/transposed gT (+bias)
// MODE 2: fp32 out = X + sig*(D+bias), with x-tile SMEM staging in last chunk
template <int MODE>
__global__ void __launch_bounds__(256, 2)
gemm128(const __nv_bfloat16* __restrict__ A, int lda,
        const __nv_bfloat16* __restrict__ B, int ldb,
        int K,
        const float* __restrict__ bias,
        const float* __restrict__ Xres, const float* __restrict__ sig,
        float* __restrict__ outf) {
    extern __shared__ char sm[];
    uint32_t base = smem_u32(sm);
    const uint32_t a_su[3] = {base, base + 16384, base + 32768};
    const uint32_t b_su[3] = {base + 49152, base + 65536, base + 81920};
    // x staging (MODE 2, last chunk): rows 0..63 at a_su[1], rows 64..127 at b_su[1]
    const uint32_t x_su[2] = {base + 16384, base + 65536};

    int tid = threadIdx.x, wid = tid >> 5, lane = tid & 31;
    int m0 = blockIdx.y * 128, n0 = blockIdx.x * 128;
    int wm = wid & 3, wn = wid >> 2;
    int lr = lane & 15, lc = lane >> 4;

    const __nv_bfloat16* Ab = A + (size_t)m0 * lda;
    const __nv_bfloat16* Bb = B + (size_t)n0 * ldb;

    float acc[2][8][4];
#pragma unroll
    for (int i = 0; i < 2; i++)
#pragma unroll
        for (int j = 0; j < 8; j++)
#pragma unroll
            for (int e = 0; e < 4; e++) acc[i][j][e] = 0.f;

    const int nc = K >> 6;
    load_tile_async<128>(Ab, (size_t)lda, a_su[0], tid);
    load_tile_async<128>(Bb, (size_t)ldb, b_su[0], tid);
    CP_COMMIT();
    if (nc > 1) {
        load_tile_async<128>(Ab + 64, (size_t)lda, a_su[1], tid);
        load_tile_async<128>(Bb + 64, (size_t)ldb, b_su[1], tid);
        CP_COMMIT();
    }

#pragma unroll 3
    for (int c = 0; c < nc; c++) {
        if (c + 2 <= nc) { CP_WAIT(1); } else { CP_WAIT(0); }
        __syncthreads();

        if (MODE == 2 && c == nc - 1) {
            // stage fp32 x tile (128x128) into dead pipeline buffers
            // thread loads 16x cp16: 64KB / 16B / 256 threads
#pragma unroll
            for (int t = 0; t < 8; t++) {
                int i = tid + t * 256;       // half-tile element (64 rows x 32 float4)
                int row = i >> 5, c4 = i & 31;
                cp16(x_su[0] + row * 512 + c4 * 16,
                     Xres + (size_t)(m0 + row) * CCH + n0 + c4 * 4);
                cp16(x_su[1] + row * 512 + c4 * 16,
                     Xres + (size_t)(m0 + 64 + row) * CCH + n0 + c4 * 4);
            }
            CP_COMMIT();
        }

        int buf = c % 3;
        uint32_t abase = a_su[buf], bbase = b_su[buf];
#pragma unroll
        for (int k16 = 0; k16 < 4; k16++) {
            uint32_t af[2][4];
#pragma unroll
            for (int mt = 0; mt < 2; mt++)
                ldsm_x4(af[mt], abase + SWZ((wm * 32 + mt * 16 + lr) * 128 + k16 * 32 + lc * 16));
            uint32_t bf4[4][4];
#pragma unroll
            for (int nt2 = 0; nt2 < 4; nt2++)
                ldsm_x4(bf4[nt2], bbase + SWZ((wn * 64 + nt2 * 16 + lr) * 128 + k16 * 32 + lc * 16));
#pragma unroll
            for (int mt = 0; mt < 2; mt++)
#pragma unroll
                for (int nt = 0; nt < 8; nt++)
                    mma16816(acc[mt][nt], af[mt], bf4[nt >> 1][nt & 1], bf4[nt >> 1][2 + (nt & 1)]);
        }

        if (c + 2 < nc) {
            int nb = (c + 2) % 3;
            load_tile_async<128>(Ab + (c + 2) * 64, (size_t)lda, a_su[nb], tid);
            load_tile_async<128>(Bb + (c + 2) * 64, (size_t)ldb, b_su[nb], tid);
            CP_COMMIT();
        }
    }

    if (MODE == 2) {
        CP_WAIT(0);        // x staging landed
        __syncthreads();
        float s = sig[0];
        int r0l = wm * 32 + (lane >> 2);
        int c0 = wn * 64 + (lane & 3) * 2;
#pragma unroll
        for (int mt = 0; mt < 2; mt++) {
#pragma unroll
            for (int half = 0; half < 2; half++) {
                int rowl = r0l + mt * 16 + half * 8;    // 0..127 local
                uint32_t xrow = x_su[rowl >> 6] + (rowl & 63) * 512;
                int grow = m0 + rowl;
#pragma unroll
                for (int nt = 0; nt < 8; nt++) {
                    int col = c0 + nt * 8;              // 0..127 local
                    float2 xv = *(const float2*)(sm + (xrow - base) + col * 4);
                    float2 o;
                    o.x = xv.x + s * (acc[mt][nt][half * 2 + 0] + bias[n0 + col]);
                    o.y = xv.y + s * (acc[mt][nt][half * 2 + 1] + bias[n0 + col + 1]);
                    *(float2*)(outf + (size_t)grow * CCH + n0 + col) = o;
                }
            }
        }
    }

    if (MODE == 0) {
        // proj epilogue with fused pooling
        int b = m0 >> 12;
        int kv0 = ((m0 >> 7) & 31) * 32;   // 32 pool windows per tile
        __nv_bfloat16* st = (__nv_bfloat16*)sm;
        __syncthreads();

        if (blockIdx.x == 0) {
            if (wn == 0) {
#pragma unroll
                for (int mt = 0; mt < 2; mt++)
#pragma unroll
                    for (int half = 0; half < 2; half++) {
                        int row = m0 + wm * 32 + (lane >> 2) + mt * 16 + half * 8;
#pragma unroll
                        for (int nt = 0; nt < 8; nt++) {
                            int col = nt * 8 + (lane & 3) * 2;
                            *(__nv_bfloat162*)(g_theta + (size_t)row * DK + col) =
                                __floats2bfloat162_rn(acc[mt][nt][half * 2] + bias[col],
                                                      acc[mt][nt][half * 2 + 1] + bias[col + 1]);
                        }
                    }
            } else {
#pragma unroll
                for (int mt = 0; mt < 2; mt++)
#pragma unroll
                    for (int half = 0; half < 2; half++) {
                        int lrow = wm * 32 + (lane >> 2) + mt * 16 + half * 8;
#pragma unroll
                        for (int nt = 0; nt < 8; nt++) {
                            int lcol = nt * 8 + (lane & 3) * 2;   // 0..63
                            *(__nv_bfloat162*)(st + lrow * 72 + lcol) =
                                __floats2bfloat162_rn(acc[mt][nt][half * 2] + bias[64 + lcol],
                                                      acc[mt][nt][half * 2 + 1] + bias[65 + lcol]);
                        }
                    }
            }
            __syncthreads();
            int w = tid >> 3, d8 = (tid & 7) * 8;
            __align__(16) __nv_bfloat16 o[8];
#pragma unroll
            for (int j = 0; j < 8; j++) {
                int d = d8 + j;
                o[j] = __hmax(__hmax(st[(2 * w) * 72 + d], st[(2 * w + 1) * 72 + d]),
                              __hmax(st[(64 + 2 * w) * 72 + d], st[(65 + 2 * w) * 72 + d]));
            }
            *(uint4*)(g_phi + ((size_t)(b * NKV + kv0 + w)) * DK + d8) = *(uint4*)o;
        } else {
#pragma unroll
            for (int mt = 0; mt < 2; mt++)
#pragma unroll
                for (int half = 0; half < 2; half++) {
                    int lrow = wm * 32 + (lane >> 2) + mt * 16 + half * 8;
#pragma unroll
                    for (int nt = 0; nt < 8; nt++) {
                        int lcol = wn * 64 + nt * 8 + (lane & 3) * 2;   // 0..127
                        *(__nv_bfloat162*)(st + lrow * 130 + lcol) =
                            __floats2bfloat162_rn(acc[mt][nt][half * 2] + bias[n0 + lcol],
                                                  acc[mt][nt][half * 2 + 1] + bias[n0 + lcol + 1]);
                    }
                }
            __syncthreads();
            int dl = tid & 127, kvh = tid >> 7;
            int dg = (blockIdx.x - 1) * 128 + dl;
            __align__(16) __nv_bfloat16 o[16];
#pragma unroll
            for (int i = 0; i < 16; i++) {
                int w = kvh * 16 + i;
                o[i] = __hmax(__hmax(st[(2 * w) * 130 + dl], st[(2 * w + 1) * 130 + dl]),
                              __hmax(st[(64 + 2 * w) * 130 + dl], st[(65 + 2 * w) * 130 + dl]));
            }
            __nv_bfloat16* dst = g_gT + ((size_t)(b * DV + dg)) * NKV + kv0 + kvh * 16;
            *(uint4*)dst = ((uint4*)o)[0];
            *(uint4*)(dst + 8) = ((uint4*)o)[1];
        }
    }
}

// ------------- fused attention: ag = softmax(theta phi^T) g ----------------
// CTA = 64 queries; loop 16 KV chunks of 64. (R7 structure; prefetch issued
// after S-phase so the cp.async burst lands in the mid-barrier shadow.)
#define ATTN_SMEM (99072)
__global__ void __launch_bounds__(256, 2) attn_fused() {
    extern __shared__ char sm[];
    uint32_t base = smem_u32(sm);
    const uint32_t th_s = base;
    const uint32_t ph_s[2] = {base + 8192, base + 16384};
    const uint32_t gt_s[2] = {base + 24576, base + 57344};
    const uint32_t p_s = base + 90112;
    float* wsum = (float*)(sm + 98304);   // [2][64]
    float* rinv = (float*)(sm + 98816);   // [64]

    int tid = threadIdx.x, wid = tid >> 5, lane = tid & 31;
    int lr = lane & 15, lc = lane >> 4;
    int mbase = blockIdx.x * 64;
    int b = blockIdx.x >> 6;
    int wm = wid & 3, wn = wid >> 2;       // S phase
    int pm = wid & 1, pn = wid >> 1;       // PV phase

    const __nv_bfloat16* thp = g_theta + (size_t)mbase * DK;
    const __nv_bfloat16* php = g_phi + (size_t)b * NKV * DK;
    const __nv_bfloat16* gtp = g_gT + (size_t)b * DV * NKV;

    float O[2][8][4];
#pragma unroll
    for (int i = 0; i < 2; i++)
#pragma unroll
        for (int j = 0; j < 8; j++)
#pragma unroll
            for (int e = 0; e < 4; e++) O[i][j][e] = 0.f;
    float sum0 = 0.f, sum1 = 0.f;

    load_tile_async<64>(thp, DK, th_s, tid);
    load_tile_async<64>(php, DK, ph_s[0], tid);
    load_tile_async<256>(gtp, NKV, gt_s[0], tid);
    CP_COMMIT();

    for (int c = 0; c < 16; c++) {
        CP_WAIT(0);
        __syncthreads();   // chunk-c tiles visible; all warps done with c-1

        // ---- S phase ----
        float sacc[4][4];
#pragma unroll
        for (int j = 0; j < 4; j++)
#pragma unroll
            for (int e = 0; e < 4; e++) sacc[j][e] = 0.f;
        uint32_t pb = ph_s[c & 1];
#pragma unroll
        for (int k16 = 0; k16 < 4; k16++) {
            uint32_t af[4];
            ldsm_x4(af, th_s + SWZ((wm * 16 + lr) * 128 + k16 * 32 + lc * 16));
            uint32_t bf2[2][4];
#pragma unroll
            for (int nt2 = 0; nt2 < 2; nt2++)
                ldsm_x4(bf2[nt2], pb + SWZ((wn * 32 + nt2 * 16 + lr) * 128 + k16 * 32 + lc * 16));
#pragma unroll
            for (int nt = 0; nt < 4; nt++)
                mma16816(sacc[nt], af, bf2[nt >> 1][nt & 1], bf2[nt >> 1][2 + (nt & 1)]);
        }

        int srow = wm * 16 + (lane >> 2);
#pragma unroll
        for (int nt = 0; nt < 4; nt++) {
            int scol = wn * 32 + nt * 8 + (lane & 3) * 2;
            float e0 = __expf(sacc[nt][0]);
            float e1 = __expf(sacc[nt][1]);
            float e2 = __expf(sacc[nt][2]);
            float e3 = __expf(sacc[nt][3]);
            sum0 += e0 + e1;
            sum1 += e2 + e3;
            *(__nv_bfloat162*)(sm + (p_s - base) + SWZ(srow * 128 + scol * 2)) =
                __floats2bfloat162_rn(e0, e1);
            *(__nv_bfloat162*)(sm + (p_s - base) + SWZ((srow + 8) * 128 + scol * 2)) =
                __floats2bfloat162_rn(e2, e3);
        }

        // prefetch c+1 — burst lands in the barrier shadow below
        if (c + 1 < 16) {
            int nb = (c + 1) & 1;
            load_tile_async<64>(php + (size_t)(c + 1) * 64 * DK, DK, ph_s[nb], tid);
            load_tile_async<256>(gtp + (c + 1) * 64, NKV, gt_s[nb], tid);
            CP_COMMIT();
        }
        __syncthreads();   // P(c) visible to all warps

        // ---- PV phase ----
        uint32_t gb = gt_s[c & 1];
#pragma unroll
        for (int k16 = 0; k16 < 4; k16++) {
            uint32_t paf[2][4];
#pragma unroll
            for (int mt = 0; mt < 2; mt++)
                ldsm_x4(paf[mt], p_s + SWZ((pm * 32 + mt * 16 + lr) * 128 + k16 * 32 + lc * 16));
            uint32_t gbf[4][4];
#pragma unroll
            for (int nt2 = 0; nt2 < 4; nt2++)
                ldsm_x4(gbf[nt2], gb + SWZ((pn * 64 + nt2 * 16 + lr) * 128 + k16 * 32 + lc * 16));
#pragma unroll
            for (int mt = 0; mt < 2; mt++)
#pragma unroll
                for (int nt = 0; nt < 8; nt++)
                    mma16816(O[mt][nt], paf[mt], gbf[nt >> 1][nt & 1], gbf[nt >> 1][2 + (nt & 1)]);
        }
    }

    // deterministic row-sum reduction
    sum0 += __shfl_xor_sync(0xffffffffu, sum0, 1);
    sum0 += __shfl_xor_sync(0xffffffffu, sum0, 2);
    sum1 += __shfl_xor_sync(0xffffffffu, sum1, 1);
    sum1 += __shfl_xor_sync(0xffffffffu, sum1, 2);
    if ((lane & 3) == 0) {
        wsum[wn * 64 + wm * 16 + (lane >> 2)] = sum0;
        wsum[wn * 64 + wm * 16 + 8 + (lane >> 2)] = sum1;
    }
    __syncthreads();
    if (tid < 64) rinv[tid] = 1.f / (wsum[tid] + wsum[64 + tid]);
    __syncthreads();

#pragma unroll
    for (int mt = 0; mt < 2; mt++) {
#pragma unroll
        for (int half = 0; half < 2; half++) {
            int row = pm * 32 + mt * 16 + half * 8 + (lane >> 2);
            float rs = rinv[row];
            __nv_bfloat16* dst = g_ag + (size_t)(mbase + row) * DV;
#pragma unroll
            for (int nt = 0; nt < 8; nt++) {
                int col = pn * 64 + nt * 8 + (lane & 3) * 2;
                *(__nv_bfloat162*)(dst + col) = __floats2bfloat162_rn(
                    O[mt][nt][half * 2 + 0] * rs, O[mt][nt][half * 2 + 1] * rs);
            }
        }
    }
}

// ---------------- small kernels ----------------
__global__ void pack_kernel(const float* __restrict__ wt, const float* __restrict__ wp,
                            const float* __restrict__ wg, const float* __restrict__ bt,
                            const float* __restrict__ bp, const float* __restrict__ bg,
                            const float* __restrict__ wo) {
    int idx = blockIdx.x * blockDim.x + threadIdx.x;
    if (idx < NPROJ * CCH) {
        int n = idx / CCH, k = idx - n * CCH;
        float v;
        if (n < 64)       v = wt[k * 64 + n];
        else if (n < 128) v = wp[k * 64 + (n - 64)];
        else              v = wg[k * 256 + (n - 128)];
        g_wcatT[idx] = __float2bfloat16(v);
    }
    if (idx < CCH * DV) {
        int n = idx / DV, k = idx - n * DV;
        g_woT[idx] = __float2bfloat16(wo[k * CCH + n]);
    }
    if (idx < NPROJ) {
        float v;
        if (idx < 64)       v = bt[idx];
        else if (idx < 128) v = bp[idx - 64];
        else                v = bg[idx - 128];
        g_bcat[idx] = v;
    }
}

__global__ void xconv_kernel(const float* __restrict__ x) {
    int i = blockIdx.x * blockDim.x + threadIdx.x;
    if (i >= M_PIX * CCH / 8) return;
    float4 a = *(const float4*)(x + (size_t)i * 8);
    float4 b = *(const float4*)(x + (size_t)i * 8 + 4);
    __nv_bfloat162 h[4];
    h[0] = __floats2bfloat162_rn(a.x, a.y);
    h[1] = __floats2bfloat162_rn(a.z, a.w);
    h[2] = __floats2bfloat162_rn(b.x, b.y);
    h[3] = __floats2bfloat162_rn(b.z, b.w);
    *(uint4*)(g_xb + (size_t)i * 8) = *(uint4*)h;
}

// ---------------- launcher ----------------
extern "C" void kernel_launch(void* const* d_in, const int* in_sizes, int n_in,
                              void* d_out, int out_size) {
    const float* x       = (const float*)d_in[0];
    const float* w_theta = (const float*)d_in[1];
    const float* b_theta = (const float*)d_in[2];
    const float* w_phi   = (const float*)d_in[3];
    const float* b_phi   = (const float*)d_in[4];
    const float* w_g     = (const float*)d_in[5];
    const float* b_g     = (const float*)d_in[6];
    const float* w_o     = (const float*)d_in[7];
    const float* b_o     = (const float*)d_in[8];
    const float* sigma   = (const float*)d_in[9];
    float* out = (float*)d_out;

    const int SMEM128 = 98304;
    cudaFuncSetAttribute((const void*)gemm128<0>, cudaFuncAttributeMaxDynamicSharedMemorySize, SMEM128);
    cudaFuncSetAttribute((const void*)gemm128<2>, cudaFuncAttributeMaxDynamicSharedMemorySize, SMEM128);
    cudaFuncSetAttribute((const void*)attn_fused, cudaFuncAttributeMaxDynamicSharedMemorySize, ATTN_SMEM);

    __nv_bfloat16 *xb, *ag, *wcatT, *woT;
    float* bcat;
    cudaGetSymbolAddress((void**)&xb, g_xb);
    cudaGetSymbolAddress((void**)&ag, g_ag);
    cudaGetSymbolAddress((void**)&wcatT, g_wcatT);
    cudaGetSymbolAddress((void**)&woT, g_woT);
    cudaGetSymbolAddress((void**)&bcat, g_bcat);

    pack_kernel<<<(NPROJ * CCH + 255) / 256, 256>>>(w_theta, w_phi, w_g,
                                                    b_theta, b_phi, b_g, w_o);
    xconv_kernel<<<M_PIX * CCH / 8 / 256, 256>>>(x);

    // proj (+fused pooling): theta/phi/gT produced directly
    gemm128<0><<<dim3(NPROJ / 128, M_PIX / 128), 256, SMEM128>>>(
        xb, CCH, wcatT, CCH, CCH, bcat, nullptr, nullptr, nullptr);

    // fused attention: ag = softmax(theta phi^T) g
    attn_fused<<<M_PIX / 64, 256, ATTN_SMEM>>>();

    // out: [65536, 512] = x + sigma * (ag[65536,256] @ woT[512,256]^T + b_o)
    gemm128<2><<<dim3(CCH / 128, M_PIX / 128), 256, SMEM128>>>(
        ag, DV, woT, DV, DV, b_o, x, sigma, out);
}

// round 11
// speedup vs baseline: 1.1962x; 1.0482x over previous
#include <cuda_runtime.h>
#include <cuda_bf16.h>
#include <cstdint>

#define BBATCH 16
#define CCH 512
#define M_PIX (BBATCH*64*64)     // 65536
#define NPROJ 384
#define DK 64
#define DV 256
#define NKV 1024
#define NQ  4096
#define LOG2E 1.4426950408889634f

// ---------------- scratch (device globals) ----------------
__device__ __align__(256) __nv_bfloat16 g_xb   [M_PIX * CCH];       // x in bf16
__device__ __align__(256) __nv_bfloat16 g_theta[M_PIX * DK];        // theta*log2e [q][64]
__device__ __align__(256) __nv_bfloat16 g_phi  [BBATCH * NKV * DK]; // pooled phi [kv][d]
__device__ __align__(256) __nv_bfloat16 g_gT   [BBATCH * DV * NKV]; // pooled g^T [d][kv]
__device__ __align__(256) __nv_bfloat16 g_ag   [M_PIX * DV];        // attn out bf16
__device__ __align__(256) __nv_bfloat16 g_wcatT[NPROJ * CCH];       // proj weights^T
__device__ __align__(256) __nv_bfloat16 g_woT  [CCH * DV];          // w_o^T
__device__ float g_bcat[NPROJ];

// ---------------- helpers ----------------
__device__ __forceinline__ uint32_t smem_u32(const void* p) {
    uint32_t a;
    asm("{ .reg .u64 t; cvta.to.shared.u64 t, %1; cvt.u32.u64 %0, t; }" : "=r"(a) : "l"(p));
    return a;
}
#define SWZ(o) ((o) ^ (((o) >> 3) & 0x70))

__device__ __forceinline__ void ldsm_x4(uint32_t* r, uint32_t a) {
    asm volatile("ldmatrix.sync.aligned.m8n8.x4.shared.b16 {%0,%1,%2,%3}, [%4];"
        : "=r"(r[0]), "=r"(r[1]), "=r"(r[2]), "=r"(r[3]) : "r"(a));
}
__device__ __forceinline__ void mma16816(float* d, const uint32_t* a, uint32_t b0, uint32_t b1) {
    asm volatile("mma.sync.aligned.m16n8k16.row.col.f32.bf16.bf16.f32 "
        "{%0,%1,%2,%3}, {%4,%5,%6,%7}, {%8,%9}, {%0,%1,%2,%3};"
        : "+f"(d[0]), "+f"(d[1]), "+f"(d[2]), "+f"(d[3])
        : "r"(a[0]), "r"(a[1]), "r"(a[2]), "r"(a[3]), "r"(b0), "r"(b1));
}
__device__ __forceinline__ void cp16(uint32_t sa, const void* ga) {
    asm volatile("cp.async.cg.shared.global [%0], [%1], 16;" :: "r"(sa), "l"(ga));
}
#define CP_COMMIT() asm volatile("cp.async.commit_group;" ::: "memory")
#define CP_WAIT(n)  asm volatile("cp.async.wait_group %0;" :: "n"(n) : "memory")

__device__ __forceinline__ float ex2(float x) {
    float r;
    asm("ex2.approx.ftz.f32 %0, %1;" : "=f"(r) : "f"(x));
    return r;
}

// load [ROWS x 64] bf16 tile (row stride ld) into swizzled SMEM via cp.async
template <int ROWS>
__device__ __forceinline__ void load_tile_async(const __nv_bfloat16* __restrict__ src,
                                                size_t ld, uint32_t sbase, int tid) {
#pragma unroll
    for (int t = 0; t < ROWS / 32; t++) {
        int i = tid + t * 256;
        int row = i >> 3, c = i & 7;
        cp16(sbase + SWZ(row * 128 + c * 16), src + (size_t)row * ld + c * 8);
    }
}

// ------------- 128x128-tile bf16 HMMA GEMM, fp32 accum, 3-stage cp.async ----
// MODE 0: proj — theta(*log2e) direct + pooled phi + pooled/transposed gT (+bias)
// MODE 2: fp32 out = X + sig*(D+bias), x tile staged via dead pipeline buffers
template <int MODE>
__global__ void __launch_bounds__(256, 2)
gemm128(const __nv_bfloat16* __restrict__ A, int lda,
        const __nv_bfloat16* __restrict__ B, int ldb,
        int K,
        const float* __restrict__ bias,
        const float* __restrict__ Xres, const float* __restrict__ sig,
        float* __restrict__ outf) {
    extern __shared__ char sm[];
    uint32_t base = smem_u32(sm);
    const uint32_t a_su[3] = {base, base + 16384, base + 32768};
    const uint32_t b_su[3] = {base + 49152, base + 65536, base + 81920};
    // x staging (MODE 2, last chunk): rows 0..63 at a_su[1], rows 64..127 at b_su[1]
    const uint32_t x_su[2] = {base + 16384, base + 65536};

    int tid = threadIdx.x, wid = tid >> 5, lane = tid & 31;
    int m0 = blockIdx.y * 128, n0 = blockIdx.x * 128;
    int wm = wid & 3, wn = wid >> 2;
    int lr = lane & 15, lc = lane >> 4;

    const __nv_bfloat16* Ab = A + (size_t)m0 * lda;
    const __nv_bfloat16* Bb = B + (size_t)n0 * ldb;

    float acc[2][8][4];
#pragma unroll
    for (int i = 0; i < 2; i++)
#pragma unroll
        for (int j = 0; j < 8; j++)
#pragma unroll
            for (int e = 0; e < 4; e++) acc[i][j][e] = 0.f;

    const int nc = K >> 6;
    load_tile_async<128>(Ab, (size_t)lda, a_su[0], tid);
    load_tile_async<128>(Bb, (size_t)ldb, b_su[0], tid);
    CP_COMMIT();
    if (nc > 1) {
        load_tile_async<128>(Ab + 64, (size_t)lda, a_su[1], tid);
        load_tile_async<128>(Bb + 64, (size_t)ldb, b_su[1], tid);
        CP_COMMIT();
    }

#pragma unroll 3
    for (int c = 0; c < nc; c++) {
        if (c + 2 <= nc) { CP_WAIT(1); } else { CP_WAIT(0); }
        __syncthreads();

        if (MODE == 2 && c == nc - 1) {
            // stage fp32 x tile (128x128) into dead pipeline buffers
#pragma unroll
            for (int t = 0; t < 8; t++) {
                int i = tid + t * 256;
                int row = i >> 5, c4 = i & 31;
                cp16(x_su[0] + row * 512 + c4 * 16,
                     Xres + (size_t)(m0 + row) * CCH + n0 + c4 * 4);
                cp16(x_su[1] + row * 512 + c4 * 16,
                     Xres + (size_t)(m0 + 64 + row) * CCH + n0 + c4 * 4);
            }
            CP_COMMIT();
        }

        int buf = c % 3;
        uint32_t abase = a_su[buf], bbase = b_su[buf];
#pragma unroll
        for (int k16 = 0; k16 < 4; k16++) {
            uint32_t af[2][4];
#pragma unroll
            for (int mt = 0; mt < 2; mt++)
                ldsm_x4(af[mt], abase + SWZ((wm * 32 + mt * 16 + lr) * 128 + k16 * 32 + lc * 16));
            uint32_t bf4[4][4];
#pragma unroll
            for (int nt2 = 0; nt2 < 4; nt2++)
                ldsm_x4(bf4[nt2], bbase + SWZ((wn * 64 + nt2 * 16 + lr) * 128 + k16 * 32 + lc * 16));
#pragma unroll
            for (int mt = 0; mt < 2; mt++)
#pragma unroll
                for (int nt = 0; nt < 8; nt++)
                    mma16816(acc[mt][nt], af[mt], bf4[nt >> 1][nt & 1], bf4[nt >> 1][2 + (nt & 1)]);
        }

        if (c + 2 < nc) {
            int nb = (c + 2) % 3;
            load_tile_async<128>(Ab + (c + 2) * 64, (size_t)lda, a_su[nb], tid);
            load_tile_async<128>(Bb + (c + 2) * 64, (size_t)ldb, b_su[nb], tid);
            CP_COMMIT();
        }
    }

    if (MODE == 2) {
        CP_WAIT(0);        // x staging landed
        __syncthreads();
        float s = sig[0];
        int r0l = wm * 32 + (lane >> 2);
        int c0 = wn * 64 + (lane & 3) * 2;
#pragma unroll
        for (int mt = 0; mt < 2; mt++) {
#pragma unroll
            for (int half = 0; half < 2; half++) {
                int rowl = r0l + mt * 16 + half * 8;
                uint32_t xrow = x_su[rowl >> 6] + (rowl & 63) * 512;
                int grow = m0 + rowl;
#pragma unroll
                for (int nt = 0; nt < 8; nt++) {
                    int col = c0 + nt * 8;
                    float2 xv = *(const float2*)(sm + (xrow - base) + col * 4);
                    float2 o;
                    o.x = xv.x + s * (acc[mt][nt][half * 2 + 0] + bias[n0 + col]);
                    o.y = xv.y + s * (acc[mt][nt][half * 2 + 1] + bias[n0 + col + 1]);
                    *(float2*)(outf + (size_t)grow * CCH + n0 + col) = o;
                }
            }
        }
    }

    if (MODE == 0) {
        // proj epilogue with fused pooling
        int b = m0 >> 12;
        int kv0 = ((m0 >> 7) & 31) * 32;   // 32 pool windows per tile
        __nv_bfloat16* st = (__nv_bfloat16*)sm;
        __syncthreads();

        if (blockIdx.x == 0) {
            if (wn == 0) {
                // theta, pre-scaled by log2e for ex2-based softmax
#pragma unroll
                for (int mt = 0; mt < 2; mt++)
#pragma unroll
                    for (int half = 0; half < 2; half++) {
                        int row = m0 + wm * 32 + (lane >> 2) + mt * 16 + half * 8;
#pragma unroll
                        for (int nt = 0; nt < 8; nt++) {
                            int col = nt * 8 + (lane & 3) * 2;
                            *(__nv_bfloat162*)(g_theta + (size_t)row * DK + col) =
                                __floats2bfloat162_rn(
                                    (acc[mt][nt][half * 2] + bias[col]) * LOG2E,
                                    (acc[mt][nt][half * 2 + 1] + bias[col + 1]) * LOG2E);
                        }
                    }
            } else {
#pragma unroll
                for (int mt = 0; mt < 2; mt++)
#pragma unroll
                    for (int half = 0; half < 2; half++) {
                        int lrow = wm * 32 + (lane >> 2) + mt * 16 + half * 8;
#pragma unroll
                        for (int nt = 0; nt < 8; nt++) {
                            int lcol = nt * 8 + (lane & 3) * 2;   // 0..63
                            *(__nv_bfloat162*)(st + lrow * 72 + lcol) =
                                __floats2bfloat162_rn(acc[mt][nt][half * 2] + bias[64 + lcol],
                                                      acc[mt][nt][half * 2 + 1] + bias[65 + lcol]);
                        }
                    }
            }
            __syncthreads();
            int w = tid >> 3, d8 = (tid & 7) * 8;
            __align__(16) __nv_bfloat16 o[8];
#pragma unroll
            for (int j = 0; j < 8; j++) {
                int d = d8 + j;
                o[j] = __hmax(__hmax(st[(2 * w) * 72 + d], st[(2 * w + 1) * 72 + d]),
                              __hmax(st[(64 + 2 * w) * 72 + d], st[(65 + 2 * w) * 72 + d]));
            }
            *(uint4*)(g_phi + ((size_t)(b * NKV + kv0 + w)) * DK + d8) = *(uint4*)o;
        } else {
#pragma unroll
            for (int mt = 0; mt < 2; mt++)
#pragma unroll
                for (int half = 0; half < 2; half++) {
                    int lrow = wm * 32 + (lane >> 2) + mt * 16 + half * 8;
#pragma unroll
                    for (int nt = 0; nt < 8; nt++) {
                        int lcol = wn * 64 + nt * 8 + (lane & 3) * 2;   // 0..127
                        *(__nv_bfloat162*)(st + lrow * 130 + lcol) =
                            __floats2bfloat162_rn(acc[mt][nt][half * 2] + bias[n0 + lcol],
                                                  acc[mt][nt][half * 2 + 1] + bias[n0 + lcol + 1]);
                    }
                }
            __syncthreads();
            int dl = tid & 127, kvh = tid >> 7;
            int dg = (blockIdx.x - 1) * 128 + dl;
            __align__(16) __nv_bfloat16 o[16];
#pragma unroll
            for (int i = 0; i < 16; i++) {
                int w = kvh * 16 + i;
                o[i] = __hmax(__hmax(st[(2 * w) * 130 + dl], st[(2 * w + 1) * 130 + dl]),
                              __hmax(st[(64 + 2 * w) * 130 + dl], st[(65 + 2 * w) * 130 + dl]));
            }
            __nv_bfloat16* dst = g_gT + ((size_t)(b * DV + dg)) * NKV + kv0 + kvh * 16;
            *(uint4*)dst = ((uint4*)o)[0];
            *(uint4*)(dst + 8) = ((uint4*)o)[1];
        }
    }
}

// ------------- fused attention: ag = softmax(theta phi^T) g ----------------
// R7 structure exactly (prefetch at top of loop); softmax via ex2 on
// pre-scaled theta.
#define ATTN_SMEM (99072)
__global__ void __launch_bounds__(256, 2) attn_fused() {
    extern __shared__ char sm[];
    uint32_t base = smem_u32(sm);
    const uint32_t th_s = base;
    const uint32_t ph_s[2] = {base + 8192, base + 16384};
    const uint32_t gt_s[2] = {base + 24576, base + 57344};
    const uint32_t p_s = base + 90112;
    float* wsum = (float*)(sm + 98304);   // [2][64]
    float* rinv = (float*)(sm + 98816);   // [64]

    int tid = threadIdx.x, wid = tid >> 5, lane = tid & 31;
    int lr = lane & 15, lc = lane >> 4;
    int mbase = blockIdx.x * 64;
    int b = blockIdx.x >> 6;
    int wm = wid & 3, wn = wid >> 2;       // S phase
    int pm = wid & 1, pn = wid >> 1;       // PV phase

    const __nv_bfloat16* thp = g_theta + (size_t)mbase * DK;
    const __nv_bfloat16* php = g_phi + (size_t)b * NKV * DK;
    const __nv_bfloat16* gtp = g_gT + (size_t)b * DV * NKV;

    float O[2][8][4];
#pragma unroll
    for (int i = 0; i < 2; i++)
#pragma unroll
        for (int j = 0; j < 8; j++)
#pragma unroll
            for (int e = 0; e < 4; e++) O[i][j][e] = 0.f;
    float sum0 = 0.f, sum1 = 0.f;

    load_tile_async<64>(thp, DK, th_s, tid);
    load_tile_async<64>(php, DK, ph_s[0], tid);
    load_tile_async<256>(gtp, NKV, gt_s[0], tid);
    CP_COMMIT();

    for (int c = 0; c < 16; c++) {
        CP_WAIT(0);
        __syncthreads();   // chunk-c tiles visible; all warps done with c-1

        if (c + 1 < 16) {  // prefetch c+1 (overlaps S+PV of c)
            int nb = (c + 1) & 1;
            load_tile_async<64>(php + (size_t)(c + 1) * 64 * DK, DK, ph_s[nb], tid);
            load_tile_async<256>(gtp + (c + 1) * 64, NKV, gt_s[nb], tid);
            CP_COMMIT();
        }

        // ---- S phase ----
        float sacc[4][4];
#pragma unroll
        for (int j = 0; j < 4; j++)
#pragma unroll
            for (int e = 0; e < 4; e++) sacc[j][e] = 0.f;
        uint32_t pb = ph_s[c & 1];
#pragma unroll
        for (int k16 = 0; k16 < 4; k16++) {
            uint32_t af[4];
            ldsm_x4(af, th_s + SWZ((wm * 16 + lr) * 128 + k16 * 32 + lc * 16));
            uint32_t bf2[2][4];
#pragma unroll
            for (int nt2 = 0; nt2 < 2; nt2++)
                ldsm_x4(bf2[nt2], pb + SWZ((wn * 32 + nt2 * 16 + lr) * 128 + k16 * 32 + lc * 16));
#pragma unroll
            for (int nt = 0; nt < 4; nt++)
                mma16816(sacc[nt], af, bf2[nt >> 1][nt & 1], bf2[nt >> 1][2 + (nt & 1)]);
        }

        int srow = wm * 16 + (lane >> 2);
#pragma unroll
        for (int nt = 0; nt < 4; nt++) {
            int scol = wn * 32 + nt * 8 + (lane & 3) * 2;
            float e0 = ex2(sacc[nt][0]);
            float e1 = ex2(sacc[nt][1]);
            float e2 = ex2(sacc[nt][2]);
            float e3 = ex2(sacc[nt][3]);
            sum0 += e0 + e1;
            sum1 += e2 + e3;
            *(__nv_bfloat162*)(sm + (p_s - base) + SWZ(srow * 128 + scol * 2)) =
                __floats2bfloat162_rn(e0, e1);
            *(__nv_bfloat162*)(sm + (p_s - base) + SWZ((srow + 8) * 128 + scol * 2)) =
                __floats2bfloat162_rn(e2, e3);
        }
        __syncthreads();   // P(c) visible to all warps

        // ---- PV phase ----
        uint32_t gb = gt_s[c & 1];
#pragma unroll
        for (int k16 = 0; k16 < 4; k16++) {
            uint32_t paf[2][4];
#pragma unroll
            for (int mt = 0; mt < 2; mt++)
                ldsm_x4(paf[mt], p_s + SWZ((pm * 32 + mt * 16 + lr) * 128 + k16 * 32 + lc * 16));
            uint32_t gbf[4][4];
#pragma unroll
            for (int nt2 = 0; nt2 < 4; nt2++)
                ldsm_x4(gbf[nt2], gb + SWZ((pn * 64 + nt2 * 16 + lr) * 128 + k16 * 32 + lc * 16));
#pragma unroll
            for (int mt = 0; mt < 2; mt++)
#pragma unroll
                for (int nt = 0; nt < 8; nt++)
                    mma16816(O[mt][nt], paf[mt], gbf[nt >> 1][nt & 1], gbf[nt >> 1][2 + (nt & 1)]);
        }
    }

    // deterministic row-sum reduction
    sum0 += __shfl_xor_sync(0xffffffffu, sum0, 1);
    sum0 += __shfl_xor_sync(0xffffffffu, sum0, 2);
    sum1 += __shfl_xor_sync(0xffffffffu, sum1, 1);
    sum1 += __shfl_xor_sync(0xffffffffu, sum1, 2);
    if ((lane & 3) == 0) {
        wsum[wn * 64 + wm * 16 + (lane >> 2)] = sum0;
        wsum[wn * 64 + wm * 16 + 8 + (lane >> 2)] = sum1;
    }
    __syncthreads();
    if (tid < 64) rinv[tid] = 1.f / (wsum[tid] + wsum[64 + tid]);
    __syncthreads();

#pragma unroll
    for (int mt = 0; mt < 2; mt++) {
#pragma unroll
        for (int half = 0; half < 2; half++) {
            int row = pm * 32 + mt * 16 + half * 8 + (lane >> 2);
            float rs = rinv[row];
            __nv_bfloat16* dst = g_ag + (size_t)(mbase + row) * DV;
#pragma unroll
            for (int nt = 0; nt < 8; nt++) {
                int col = pn * 64 + nt * 8 + (lane & 3) * 2;
                *(__nv_bfloat162*)(dst + col) = __floats2bfloat162_rn(
                    O[mt][nt][half * 2 + 0] * rs, O[mt][nt][half * 2 + 1] * rs);
            }
        }
    }
}

// ---------------- prep: xconv + weight pack in one launch ----------------
#define XCONV_BLOCKS (M_PIX * CCH / 8 / 256)   // 16384
__global__ void prep_kernel(const float* __restrict__ x,
                            const float* __restrict__ wt, const float* __restrict__ wp,
                            const float* __restrict__ wg, const float* __restrict__ bt,
                            const float* __restrict__ bp, const float* __restrict__ bg,
                            const float* __restrict__ wo) {
    int bx = blockIdx.x;
    if (bx < XCONV_BLOCKS) {
        int i = bx * blockDim.x + threadIdx.x;  // 8 elems each
        float4 a = *(const float4*)(x + (size_t)i * 8);
        float4 b = *(const float4*)(x + (size_t)i * 8 + 4);
        __nv_bfloat162 h[4];
        h[0] = __floats2bfloat162_rn(a.x, a.y);
        h[1] = __floats2bfloat162_rn(a.z, a.w);
        h[2] = __floats2bfloat162_rn(b.x, b.y);
        h[3] = __floats2bfloat162_rn(b.z, b.w);
        *(uint4*)(g_xb + (size_t)i * 8) = *(uint4*)h;
        return;
    }
    int idx = (bx - XCONV_BLOCKS) * blockDim.x + threadIdx.x;
    if (idx < NPROJ * CCH) {
        int n = idx / CCH, k = idx - n * CCH;
        float v;
        if (n < 64)       v = wt[k * 64 + n];
        else if (n < 128) v = wp[k * 64 + (n - 64)];
        else              v = wg[k * 256 + (n - 128)];
        g_wcatT[idx] = __float2bfloat16(v);
    }
    if (idx < CCH * DV) {
        int n = idx / DV, k = idx - n * DV;
        g_woT[idx] = __float2bfloat16(wo[k * CCH + n]);
    }
    if (idx < NPROJ) {
        float v;
        if (idx < 64)       v = bt[idx];
        else if (idx < 128) v = bp[idx - 64];
        else                v = bg[idx - 128];
        g_bcat[idx] = v;
    }
}

// ---------------- launcher ----------------
extern "C" void kernel_launch(void* const* d_in, const int* in_sizes, int n_in,
                              void* d_out, int out_size) {
    const float* x       = (const float*)d_in[0];
    const float* w_theta = (const float*)d_in[1];
    const float* b_theta = (const float*)d_in[2];
    const float* w_phi   = (const float*)d_in[3];
    const float* b_phi   = (const float*)d_in[4];
    const float* w_g     = (const float*)d_in[5];
    const float* b_g     = (const float*)d_in[6];
    const float* w_o     = (const float*)d_in[7];
    const float* b_o     = (const float*)d_in[8];
    const float* sigma   = (const float*)d_in[9];
    float* out = (float*)d_out;

    const int SMEM128 = 98304;
    cudaFuncSetAttribute((const void*)gemm128<0>, cudaFuncAttributeMaxDynamicSharedMemorySize, SMEM128);
    cudaFuncSetAttribute((const void*)gemm128<2>, cudaFuncAttributeMaxDynamicSharedMemorySize, SMEM128);
    cudaFuncSetAttribute((const void*)attn_fused, cudaFuncAttributeMaxDynamicSharedMemorySize, ATTN_SMEM);

    __nv_bfloat16 *xb, *ag, *wcatT, *woT;
    float* bcat;
    cudaGetSymbolAddress((void**)&xb, g_xb);
    cudaGetSymbolAddress((void**)&ag, g_ag);
    cudaGetSymbolAddress((void**)&wcatT, g_wcatT);
    cudaGetSymbolAddress((void**)&woT, g_woT);
    cudaGetSymbolAddress((void**)&bcat, g_bcat);

    // prep: x -> bf16 and weight packing in one launch
    prep_kernel<<<XCONV_BLOCKS + (NPROJ * CCH + 255) / 256, 256>>>(
        x, w_theta, w_phi, w_g, b_theta, b_phi, b_g, w_o);

    // proj (+fused pooling): theta/phi/gT produced directly
    gemm128<0><<<dim3(NPROJ / 128, M_PIX / 128), 256, SMEM128>>>(
        xb, CCH, wcatT, CCH, CCH, bcat, nullptr, nullptr, nullptr);

    // fused attention: ag = softmax(theta phi^T) g
    attn_fused<<<M_PIX / 64, 256, ATTN_SMEM>>>();

    // out: [65536, 512] = x + sigma * (ag[65536,256] @ woT[512,256]^T + b_o)
    gemm128<2><<<dim3(CCH / 128, M_PIX / 128), 256, SMEM128>>>(
        ag, DV, woT, DV, DV, b_o, x, sigma, out);
}

// round 13
// speedup vs baseline: 1.2769x; 1.0675x over previous
#include <cuda_runtime.h>
#include <cuda_bf16.h>
#include <cstdint>

#define BBATCH 16
#define CCH 512
#define M_PIX (BBATCH*64*64)     // 65536
#define NPROJ 384
#define DK 64
#define DV 256
#define NKV 1024
#define NQ  4096
#define LOG2E 1.4426950408889634f

// ---------------- scratch (device globals) ----------------
__device__ __align__(256) __nv_bfloat16 g_xb   [M_PIX * CCH];       // x in bf16
__device__ __align__(256) __nv_bfloat16 g_theta[M_PIX * DK];        // theta*log2e [q][64]
__device__ __align__(256) __nv_bfloat16 g_phi  [BBATCH * NKV * DK]; // pooled phi [kv][d]
__device__ __align__(256) __nv_bfloat16 g_gT   [BBATCH * DV * NKV]; // pooled g^T [d][kv]
__device__ __align__(256) __nv_bfloat16 g_ag   [M_PIX * DV];        // attn out bf16
__device__ __align__(256) __nv_bfloat16 g_wcatT[NPROJ * CCH];       // proj weights^T
__device__ __align__(256) __nv_bfloat16 g_woT  [CCH * DV];          // w_o^T
__device__ float g_bcat[NPROJ];

// ---------------- helpers ----------------
__device__ __forceinline__ uint32_t smem_u32(const void* p) {
    uint32_t a;
    asm("{ .reg .u64 t; cvta.to.shared.u64 t, %1; cvt.u32.u64 %0, t; }" : "=r"(a) : "l"(p));
    return a;
}
#define SWZ(o) ((o) ^ (((o) >> 3) & 0x70))

__device__ __forceinline__ void ldsm_x4(uint32_t* r, uint32_t a) {
    asm volatile("ldmatrix.sync.aligned.m8n8.x4.shared.b16 {%0,%1,%2,%3}, [%4];"
        : "=r"(r[0]), "=r"(r[1]), "=r"(r[2]), "=r"(r[3]) : "r"(a));
}
__device__ __forceinline__ void mma16816(float* d, const uint32_t* a, uint32_t b0, uint32_t b1) {
    asm volatile("mma.sync.aligned.m16n8k16.row.col.f32.bf16.bf16.f32 "
        "{%0,%1,%2,%3}, {%4,%5,%6,%7}, {%8,%9}, {%0,%1,%2,%3};"
        : "+f"(d[0]), "+f"(d[1]), "+f"(d[2]), "+f"(d[3])
        : "r"(a[0]), "r"(a[1]), "r"(a[2]), "r"(a[3]), "r"(b0), "r"(b1));
}
__device__ __forceinline__ void cp16(uint32_t sa, const void* ga) {
    asm volatile("cp.async.cg.shared.global [%0], [%1], 16;" :: "r"(sa), "l"(ga));
}
#define CP_COMMIT() asm volatile("cp.async.commit_group;" ::: "memory")
#define CP_WAIT(n)  asm volatile("cp.async.wait_group %0;" :: "n"(n) : "memory")

__device__ __forceinline__ float ex2(float x) {
    float r;
    asm("ex2.approx.ftz.f32 %0, %1;" : "=f"(r) : "f"(x));
    return r;
}

// load [ROWS x 64] bf16 tile (row stride ld) into swizzled SMEM via cp.async
template <int ROWS>
__device__ __forceinline__ void load_tile_async(const __nv_bfloat16* __restrict__ src,
                                                size_t ld, uint32_t sbase, int tid) {
#pragma unroll
    for (int t = 0; t < ROWS / 32; t++) {
        int i = tid + t * 256;
        int row = i >> 3, c = i & 7;
        cp16(sbase + SWZ(row * 128 + c * 16), src + (size_t)row * ld + c * 8);
    }
}

// ------------- 128x128-tile bf16 HMMA GEMM, fp32 accum, 3-stage cp.async ----
// MODE 0: proj — theta(*log2e) direct + pooled phi + pooled/transposed gT (+bias)
// MODE 2: fp32 out = X + sig*(D+bias), x tile staged in LAST chunk (R11 logic:
//         staging spills into buf2, which is only safe once chunk2 is consumed)
template <int MODE>
__global__ void __launch_bounds__(256, 2)
gemm128(const __nv_bfloat16* __restrict__ A, int lda,
        const __nv_bfloat16* __restrict__ B, int ldb,
        int K, int moff,
        const float* __restrict__ bias,
        const float* __restrict__ Xres, const float* __restrict__ sig,
        float* __restrict__ outf) {
    extern __shared__ char sm[];
    uint32_t base = smem_u32(sm);
    const uint32_t a_su[3] = {base, base + 16384, base + 32768};
    const uint32_t b_su[3] = {base + 49152, base + 65536, base + 81920};
    // x staging (MODE 2, last chunk): rows 0..63 from a_su[1], rows 64..127 from b_su[1]
    const uint32_t x_su[2] = {base + 16384, base + 65536};

    int tid = threadIdx.x, wid = tid >> 5, lane = tid & 31;
    int m0 = (blockIdx.y + moff) * 128, n0 = blockIdx.x * 128;
    int wm = wid & 3, wn = wid >> 2;
    int lr = lane & 15, lc = lane >> 4;

    const __nv_bfloat16* Ab = A + (size_t)m0 * lda;
    const __nv_bfloat16* Bb = B + (size_t)n0 * ldb;

    float acc[2][8][4];
#pragma unroll
    for (int i = 0; i < 2; i++)
#pragma unroll
        for (int j = 0; j < 8; j++)
#pragma unroll
            for (int e = 0; e < 4; e++) acc[i][j][e] = 0.f;

    const int nc = K >> 6;
    load_tile_async<128>(Ab, (size_t)lda, a_su[0], tid);
    load_tile_async<128>(Bb, (size_t)ldb, b_su[0], tid);
    CP_COMMIT();
    if (nc > 1) {
        load_tile_async<128>(Ab + 64, (size_t)lda, a_su[1], tid);
        load_tile_async<128>(Bb + 64, (size_t)ldb, b_su[1], tid);
        CP_COMMIT();
    }

#pragma unroll 3
    for (int c = 0; c < nc; c++) {
        if (c + 2 <= nc) { CP_WAIT(1); } else { CP_WAIT(0); }
        __syncthreads();

        if (MODE == 2 && c == nc - 1) {
            // stage fp32 x tile (128x128 = 64KB) into pipeline buffers 1+2
            // (all chunks except the current buf0 are consumed by now)
#pragma unroll
            for (int t = 0; t < 8; t++) {
                int i = tid + t * 256;
                int row = i >> 5, c4 = i & 31;
                cp16(x_su[0] + row * 512 + c4 * 16,
                     Xres + (size_t)(m0 + row) * CCH + n0 + c4 * 4);
                cp16(x_su[1] + row * 512 + c4 * 16,
                     Xres + (size_t)(m0 + 64 + row) * CCH + n0 + c4 * 4);
            }
            CP_COMMIT();
        }

        int buf = c % 3;
        uint32_t abase = a_su[buf], bbase = b_su[buf];
#pragma unroll
        for (int k16 = 0; k16 < 4; k16++) {
            uint32_t af[2][4];
#pragma unroll
            for (int mt = 0; mt < 2; mt++)
                ldsm_x4(af[mt], abase + SWZ((wm * 32 + mt * 16 + lr) * 128 + k16 * 32 + lc * 16));
            uint32_t bf4[4][4];
#pragma unroll
            for (int nt2 = 0; nt2 < 4; nt2++)
                ldsm_x4(bf4[nt2], bbase + SWZ((wn * 64 + nt2 * 16 + lr) * 128 + k16 * 32 + lc * 16));
#pragma unroll
            for (int mt = 0; mt < 2; mt++)
#pragma unroll
                for (int nt = 0; nt < 8; nt++)
                    mma16816(acc[mt][nt], af[mt], bf4[nt >> 1][nt & 1], bf4[nt >> 1][2 + (nt & 1)]);
        }

        if (c + 2 < nc) {
            int nb = (c + 2) % 3;
            load_tile_async<128>(Ab + (c + 2) * 64, (size_t)lda, a_su[nb], tid);
            load_tile_async<128>(Bb + (c + 2) * 64, (size_t)ldb, b_su[nb], tid);
            CP_COMMIT();
        }
    }

    if (MODE == 2) {
        CP_WAIT(0);        // x staging landed
        __syncthreads();
        float s = sig[0];
        int r0l = wm * 32 + (lane >> 2);
        int c0 = wn * 64 + (lane & 3) * 2;
#pragma unroll
        for (int mt = 0; mt < 2; mt++) {
#pragma unroll
            for (int half = 0; half < 2; half++) {
                int rowl = r0l + mt * 16 + half * 8;
                uint32_t xrow = x_su[rowl >> 6] + (rowl & 63) * 512;
                int grow = m0 + rowl;
#pragma unroll
                for (int nt = 0; nt < 8; nt++) {
                    int col = c0 + nt * 8;
                    float2 xv = *(const float2*)(sm + (xrow - base) + col * 4);
                    float2 o;
                    o.x = xv.x + s * (acc[mt][nt][half * 2 + 0] + bias[n0 + col]);
                    o.y = xv.y + s * (acc[mt][nt][half * 2 + 1] + bias[n0 + col + 1]);
                    *(float2*)(outf + (size_t)grow * CCH + n0 + col) = o;
                }
            }
        }
    }

    if (MODE == 0) {
        // proj epilogue with fused pooling
        int b = m0 >> 12;
        int kv0 = ((m0 >> 7) & 31) * 32;   // 32 pool windows per tile
        __nv_bfloat16* st = (__nv_bfloat16*)sm;
        __syncthreads();

        if (blockIdx.x == 0) {
            if (wn == 0) {
                // theta, pre-scaled by log2e for ex2-based softmax
#pragma unroll
                for (int mt = 0; mt < 2; mt++)
#pragma unroll
                    for (int half = 0; half < 2; half++) {
                        int row = m0 + wm * 32 + (lane >> 2) + mt * 16 + half * 8;
#pragma unroll
                        for (int nt = 0; nt < 8; nt++) {
                            int col = nt * 8 + (lane & 3) * 2;
                            *(__nv_bfloat162*)(g_theta + (size_t)row * DK + col) =
                                __floats2bfloat162_rn(
                                    (acc[mt][nt][half * 2] + bias[col]) * LOG2E,
                                    (acc[mt][nt][half * 2 + 1] + bias[col + 1]) * LOG2E);
                        }
                    }
            } else {
#pragma unroll
                for (int mt = 0; mt < 2; mt++)
#pragma unroll
                    for (int half = 0; half < 2; half++) {
                        int lrow = wm * 32 + (lane >> 2) + mt * 16 + half * 8;
#pragma unroll
                        for (int nt = 0; nt < 8; nt++) {
                            int lcol = nt * 8 + (lane & 3) * 2;   // 0..63
                            *(__nv_bfloat162*)(st + lrow * 72 + lcol) =
                                __floats2bfloat162_rn(acc[mt][nt][half * 2] + bias[64 + lcol],
                                                      acc[mt][nt][half * 2 + 1] + bias[65 + lcol]);
                        }
                    }
            }
            __syncthreads();
            int w = tid >> 3, d8 = (tid & 7) * 8;
            __align__(16) __nv_bfloat16 o[8];
#pragma unroll
            for (int j = 0; j < 8; j++) {
                int d = d8 + j;
                o[j] = __hmax(__hmax(st[(2 * w) * 72 + d], st[(2 * w + 1) * 72 + d]),
                              __hmax(st[(64 + 2 * w) * 72 + d], st[(65 + 2 * w) * 72 + d]));
            }
            *(uint4*)(g_phi + ((size_t)(b * NKV + kv0 + w)) * DK + d8) = *(uint4*)o;
        } else {
#pragma unroll
            for (int mt = 0; mt < 2; mt++)
#pragma unroll
                for (int half = 0; half < 2; half++) {
                    int lrow = wm * 32 + (lane >> 2) + mt * 16 + half * 8;
#pragma unroll
                    for (int nt = 0; nt < 8; nt++) {
                        int lcol = wn * 64 + nt * 8 + (lane & 3) * 2;   // 0..127
                        *(__nv_bfloat162*)(st + lrow * 130 + lcol) =
                            __floats2bfloat162_rn(acc[mt][nt][half * 2] + bias[n0 + lcol],
                                                  acc[mt][nt][half * 2 + 1] + bias[n0 + lcol + 1]);
                    }
                }
            __syncthreads();
            int dl = tid & 127, kvh = tid >> 7;
            int dg = (blockIdx.x - 1) * 128 + dl;
            __align__(16) __nv_bfloat16 o[16];
#pragma unroll
            for (int i = 0; i < 16; i++) {
                int w = kvh * 16 + i;
                o[i] = __hmax(__hmax(st[(2 * w) * 130 + dl], st[(2 * w + 1) * 130 + dl]),
                              __hmax(st[(64 + 2 * w) * 130 + dl], st[(65 + 2 * w) * 130 + dl]));
            }
            __nv_bfloat16* dst = g_gT + ((size_t)(b * DV + dg)) * NKV + kv0 + kvh * 16;
            *(uint4*)dst = ((uint4*)o)[0];
            *(uint4*)(dst + 8) = ((uint4*)o)[1];
        }
    }
}

// ------------- fused attention: ag = softmax(theta phi^T) g ----------------
#define ATTN_SMEM (99072)
__global__ void __launch_bounds__(256, 2) attn_fused(int toff) {
    extern __shared__ char sm[];
    uint32_t base = smem_u32(sm);
    const uint32_t th_s = base;
    const uint32_t ph_s[2] = {base + 8192, base + 16384};
    const uint32_t gt_s[2] = {base + 24576, base + 57344};
    const uint32_t p_s = base + 90112;
    float* wsum = (float*)(sm + 98304);   // [2][64]
    float* rinv = (float*)(sm + 98816);   // [64]

    int tid = threadIdx.x, wid = tid >> 5, lane = tid & 31;
    int lr = lane & 15, lc = lane >> 4;
    int tile = blockIdx.x + toff;
    int mbase = tile * 64;
    int b = tile >> 6;
    int wm = wid & 3, wn = wid >> 2;       // S phase
    int pm = wid & 1, pn = wid >> 1;       // PV phase

    const __nv_bfloat16* thp = g_theta + (size_t)mbase * DK;
    const __nv_bfloat16* php = g_phi + (size_t)b * NKV * DK;
    const __nv_bfloat16* gtp = g_gT + (size_t)b * DV * NKV;

    float O[2][8][4];
#pragma unroll
    for (int i = 0; i < 2; i++)
#pragma unroll
        for (int j = 0; j < 8; j++)
#pragma unroll
            for (int e = 0; e < 4; e++) O[i][j][e] = 0.f;
    float sum0 = 0.f, sum1 = 0.f;

    load_tile_async<64>(thp, DK, th_s, tid);
    load_tile_async<64>(php, DK, ph_s[0], tid);
    load_tile_async<256>(gtp, NKV, gt_s[0], tid);
    CP_COMMIT();

    for (int c = 0; c < 16; c++) {
        CP_WAIT(0);
        __syncthreads();   // chunk-c tiles visible; all warps done with c-1

        if (c + 1 < 16) {  // prefetch c+1 (overlaps S+PV of c)
            int nb = (c + 1) & 1;
            load_tile_async<64>(php + (size_t)(c + 1) * 64 * DK, DK, ph_s[nb], tid);
            load_tile_async<256>(gtp + (c + 1) * 64, NKV, gt_s[nb], tid);
            CP_COMMIT();
        }

        // ---- S phase ----
        float sacc[4][4];
#pragma unroll
        for (int j = 0; j < 4; j++)
#pragma unroll
            for (int e = 0; e < 4; e++) sacc[j][e] = 0.f;
        uint32_t pb = ph_s[c & 1];
#pragma unroll
        for (int k16 = 0; k16 < 4; k16++) {
            uint32_t af[4];
            ldsm_x4(af, th_s + SWZ((wm * 16 + lr) * 128 + k16 * 32 + lc * 16));
            uint32_t bf2[2][4];
#pragma unroll
            for (int nt2 = 0; nt2 < 2; nt2++)
                ldsm_x4(bf2[nt2], pb + SWZ((wn * 32 + nt2 * 16 + lr) * 128 + k16 * 32 + lc * 16));
#pragma unroll
            for (int nt = 0; nt < 4; nt++)
                mma16816(sacc[nt], af, bf2[nt >> 1][nt & 1], bf2[nt >> 1][2 + (nt & 1)]);
        }

        int srow = wm * 16 + (lane >> 2);
#pragma unroll
        for (int nt = 0; nt < 4; nt++) {
            int scol = wn * 32 + nt * 8 + (lane & 3) * 2;
            float e0 = ex2(sacc[nt][0]);
            float e1 = ex2(sacc[nt][1]);
            float e2 = ex2(sacc[nt][2]);
            float e3 = ex2(sacc[nt][3]);
            sum0 += e0 + e1;
            sum1 += e2 + e3;
            *(__nv_bfloat162*)(sm + (p_s - base) + SWZ(srow * 128 + scol * 2)) =
                __floats2bfloat162_rn(e0, e1);
            *(__nv_bfloat162*)(sm + (p_s - base) + SWZ((srow + 8) * 128 + scol * 2)) =
                __floats2bfloat162_rn(e2, e3);
        }
        __syncthreads();   // P(c) visible to all warps

        // ---- PV phase ----
        uint32_t gb = gt_s[c & 1];
#pragma unroll
        for (int k16 = 0; k16 < 4; k16++) {
            uint32_t paf[2][4];
#pragma unroll
            for (int mt = 0; mt < 2; mt++)
                ldsm_x4(paf[mt], p_s + SWZ((pm * 32 + mt * 16 + lr) * 128 + k16 * 32 + lc * 16));
            uint32_t gbf[4][4];
#pragma unroll
            for (int nt2 = 0; nt2 < 4; nt2++)
                ldsm_x4(gbf[nt2], gb + SWZ((pn * 64 + nt2 * 16 + lr) * 128 + k16 * 32 + lc * 16));
#pragma unroll
            for (int mt = 0; mt < 2; mt++)
#pragma unroll
                for (int nt = 0; nt < 8; nt++)
                    mma16816(O[mt][nt], paf[mt], gbf[nt >> 1][nt & 1], gbf[nt >> 1][2 + (nt & 1)]);
        }
    }

    // deterministic row-sum reduction
    sum0 += __shfl_xor_sync(0xffffffffu, sum0, 1);
    sum0 += __shfl_xor_sync(0xffffffffu, sum0, 2);
    sum1 += __shfl_xor_sync(0xffffffffu, sum1, 1);
    sum1 += __shfl_xor_sync(0xffffffffu, sum1, 2);
    if ((lane & 3) == 0) {
        wsum[wn * 64 + wm * 16 + (lane >> 2)] = sum0;
        wsum[wn * 64 + wm * 16 + 8 + (lane >> 2)] = sum1;
    }
    __syncthreads();
    if (tid < 64) rinv[tid] = 1.f / (wsum[tid] + wsum[64 + tid]);
    __syncthreads();

#pragma unroll
    for (int mt = 0; mt < 2; mt++) {
#pragma unroll
        for (int half = 0; half < 2; half++) {
            int row = pm * 32 + mt * 16 + half * 8 + (lane >> 2);
            float rs = rinv[row];
            __nv_bfloat16* dst = g_ag + (size_t)(mbase + row) * DV;
#pragma unroll
            for (int nt = 0; nt < 8; nt++) {
                int col = pn * 64 + nt * 8 + (lane & 3) * 2;
                *(__nv_bfloat162*)(dst + col) = __floats2bfloat162_rn(
                    O[mt][nt][half * 2 + 0] * rs, O[mt][nt][half * 2 + 1] * rs);
            }
        }
    }
}

// ---------------- prep: xconv (half) + optional weight pack ----------------
__global__ void prep_kernel(const float* __restrict__ x,
                            const float* __restrict__ wt, const float* __restrict__ wp,
                            const float* __restrict__ wg, const float* __restrict__ bt,
                            const float* __restrict__ bp, const float* __restrict__ bg,
                            const float* __restrict__ wo,
                            int xblocks, int xoff) {
    int bx = blockIdx.x;
    if (bx < xblocks) {
        int i = (bx + xoff) * blockDim.x + threadIdx.x;  // 8 elems each
        float4 a = *(const float4*)(x + (size_t)i * 8);
        float4 b = *(const float4*)(x + (size_t)i * 8 + 4);
        __nv_bfloat162 h[4];
        h[0] = __floats2bfloat162_rn(a.x, a.y);
        h[1] = __floats2bfloat162_rn(a.z, a.w);
        h[2] = __floats2bfloat162_rn(b.x, b.y);
        h[3] = __floats2bfloat162_rn(b.z, b.w);
        *(uint4*)(g_xb + (size_t)i * 8) = *(uint4*)h;
        return;
    }
    int idx = (bx - xblocks) * blockDim.x + threadIdx.x;
    if (idx < NPROJ * CCH) {
        int n = idx / CCH, k = idx - n * CCH;
        float v;
        if (n < 64)       v = wt[k * 64 + n];
        else if (n < 128) v = wp[k * 64 + (n - 64)];
        else              v = wg[k * 256 + (n - 128)];
        g_wcatT[idx] = __float2bfloat16(v);
    }
    if (idx < CCH * DV) {
        int n = idx / DV, k = idx - n * DV;
        g_woT[idx] = __float2bfloat16(wo[k * CCH + n]);
    }
    if (idx < NPROJ) {
        float v;
        if (idx < 64)       v = bt[idx];
        else if (idx < 128) v = bp[idx - 64];
        else                v = bg[idx - 128];
        g_bcat[idx] = v;
    }
}

// ---------------- streams/events (host objects; created once pre-main) -----
static cudaStream_t g_s2;
static cudaEvent_t g_evFork, g_evPrepA, g_evJoin;
static struct StreamInit {
    StreamInit() {
        cudaStreamCreateWithFlags(&g_s2, cudaStreamNonBlocking);
        cudaEventCreateWithFlags(&g_evFork, cudaEventDisableTiming);
        cudaEventCreateWithFlags(&g_evPrepA, cudaEventDisableTiming);
        cudaEventCreateWithFlags(&g_evJoin, cudaEventDisableTiming);
    }
} g_stream_init;

// ---------------- launcher ----------------
#define XHALF_BLOCKS (M_PIX * CCH / 8 / 256 / 2)   // 8192
extern "C" void kernel_launch(void* const* d_in, const int* in_sizes, int n_in,
                              void* d_out, int out_size) {
    const float* x       = (const float*)d_in[0];
    const float* w_theta = (const float*)d_in[1];
    const float* b_theta = (const float*)d_in[2];
    const float* w_phi   = (const float*)d_in[3];
    const float* b_phi   = (const float*)d_in[4];
    const float* w_g     = (const float*)d_in[5];
    const float* b_g     = (const float*)d_in[6];
    const float* w_o     = (const float*)d_in[7];
    const float* b_o     = (const float*)d_in[8];
    const float* sigma   = (const float*)d_in[9];
    float* out = (float*)d_out;

    const int SMEM128 = 98304;
    cudaFuncSetAttribute((const void*)gemm128<0>, cudaFuncAttributeMaxDynamicSharedMemorySize, SMEM128);
    cudaFuncSetAttribute((const void*)gemm128<2>, cudaFuncAttributeMaxDynamicSharedMemorySize, SMEM128);
    cudaFuncSetAttribute((const void*)attn_fused, cudaFuncAttributeMaxDynamicSharedMemorySize, ATTN_SMEM);

    __nv_bfloat16 *xb, *ag, *wcatT, *woT;
    float* bcat;
    cudaGetSymbolAddress((void**)&xb, g_xb);
    cudaGetSymbolAddress((void**)&ag, g_ag);
    cudaGetSymbolAddress((void**)&wcatT, g_wcatT);
    cudaGetSymbolAddress((void**)&woT, g_woT);
    cudaGetSymbolAddress((void**)&bcat, g_bcat);

    // fork second stream off the capture (default) stream
    cudaEventRecord(g_evFork, 0);
    cudaStreamWaitEvent(g_s2, g_evFork, 0);

    // ---- half A (batches 0-7) on default stream; carries weight packing ----
    prep_kernel<<<XHALF_BLOCKS + (NPROJ * CCH + 255) / 256, 256>>>(
        x, w_theta, w_phi, w_g, b_theta, b_phi, b_g, w_o, XHALF_BLOCKS, 0);
    cudaEventRecord(g_evPrepA, 0);

    gemm128<0><<<dim3(NPROJ / 128, 256), 256, SMEM128>>>(
        xb, CCH, wcatT, CCH, CCH, 0, bcat, nullptr, nullptr, nullptr);
    attn_fused<<<512, 256, ATTN_SMEM>>>(0);
    gemm128<2><<<dim3(CCH / 128, 256), 256, SMEM128>>>(
        ag, DV, woT, DV, DV, 0, b_o, x, sigma, out);

    // ---- half B (batches 8-15) on second stream ----
    prep_kernel<<<XHALF_BLOCKS, 256, 0, g_s2>>>(
        x, w_theta, w_phi, w_g, b_theta, b_phi, b_g, w_o, XHALF_BLOCKS, XHALF_BLOCKS);
    cudaStreamWaitEvent(g_s2, g_evPrepA, 0);   // needs weights from half A
    gemm128<0><<<dim3(NPROJ / 128, 256), 256, SMEM128, g_s2>>>(
        xb, CCH, wcatT, CCH, CCH, 256, bcat, nullptr, nullptr, nullptr);
    attn_fused<<<512, 256, ATTN_SMEM, g_s2>>>(512);
    gemm128<2><<<dim3(CCH / 128, 256), 256, SMEM128, g_s2>>>(
        ag, DV, woT, DV, DV, 256, b_o, x, sigma, out);

    // join
    cudaEventRecord(g_evJoin, g_s2);
    cudaStreamWaitEvent(0, g_evJoin, 0);
}